// round 1
// baseline (speedup 1.0000x reference)
#include <cuda_runtime.h>
#include <stdint.h>

// HPSS: harmonic/percussive source separation.
// S: (2,2,1025,1024) fp32. harm = median_31 along W (time), perc = median_31 along H (freq),
// zero padding 15 each side. masks: m_h = h^2/(h^2+p^2), m_p = p^2/(p^2+h^2) (after Z-normalize).
// out = concat(S*m_h, S*m_p).

#define HALF 15
#define NIMG 4
#define HH 1025
#define WW 1024
#define NTOT (NIMG * HH * WW)   // 4,198,400

// scratch for harmonic median (alloc-free rule: __device__ global)
__device__ float g_harm[NTOT];

__device__ __forceinline__ void ce(float &a, float &b) {
    float lo = fminf(a, b);
    float hi = fmaxf(a, b);
    a = lo;
    b = hi;
}

// Batcher odd-even mergesort for arbitrary N (pow2 network with out-of-range
// comparators dropped == padding with +inf, which is valid). All loop bounds
// become compile-time constants after unrolling -> register-resident arrays.
template <int N>
__device__ __forceinline__ void bsort(float *a) {
#pragma unroll
    for (int p = 1; p < N; p <<= 1) {
#pragma unroll
        for (int k = p; k >= 1; k >>= 1) {
#pragma unroll
            for (int j = k % p; j + k < N; j += 2 * k) {
#pragma unroll
                for (int i = 0; i < k; ++i) {
                    if (i + j + k < N) {
                        if ((i + j) / (2 * p) == (i + j + k) / (2 * p)) {
                            ce(a[i + j], a[i + j + k]);
                        }
                    }
                }
            }
        }
    }
}

// median of 31 = union(sorted core of 28, 3 extras).
// The answer is always at sorted index 3 of {c[12],c[13],c[14],c[15],e0,e1,e2}.
__device__ __forceinline__ float med31(const float *c, float e0, float e1, float e2) {
    float v[7] = {c[12], c[13], c[14], c[15], e0, e1, e2};
    bsort<7>(v);
    return v[3];
}

// ---------------- harmonic: median along W (innermost axis) ----------------
// One block per row (1024 cols). Row staged in smem with zero pads; each
// thread computes 4 consecutive outputs via float4 smem reads (conflict-free).
__global__ __launch_bounds__(256) void harm_kernel(const float *__restrict__ S,
                                                   float *__restrict__ H) {
    __shared__ __align__(16) float sm[HALF + WW + HALF + 10];  // 1064 floats
    const int row = blockIdx.x;  // 0..4099
    const float *rp = S + (size_t)row * WW;
    const int t = threadIdx.x;

    if (t < HALF) sm[t] = 0.0f;
    if (t < HALF + 10) sm[HALF + WW + t] = 0.0f;
#pragma unroll
    for (int i = 0; i < 4; ++i) sm[HALF + t + 256 * i] = rp[t + 256 * i];
    __syncthreads();

    // window for outputs [4t .. 4t+3]: x[k] = sm[4t + k], k = 0..33 (+2 overread)
    float x[36];
#pragma unroll
    for (int q = 0; q < 9; ++q) {
        float4 v = *(const float4 *)&sm[4 * t + 4 * q];
        x[4 * q + 0] = v.x;
        x[4 * q + 1] = v.y;
        x[4 * q + 2] = v.z;
        x[4 * q + 3] = v.w;
    }

    float c[28];
#pragma unroll
    for (int i = 0; i < 28; ++i) c[i] = x[3 + i];
    bsort<28>(c);

    float m0 = med31(c, x[0], x[1], x[2]);
    float m1 = med31(c, x[1], x[2], x[31]);
    float m2 = med31(c, x[2], x[31], x[32]);
    float m3 = med31(c, x[31], x[32], x[33]);

    float4 *hp = (float4 *)(H + (size_t)row * WW + 4 * t);
    *hp = make_float4(m0, m1, m2, m3);
}

// ------- percussive: median along H (freq axis) + fused softmask/outputs -------
// threadIdx.x = column (coalesced), each thread computes 4 consecutive-row outputs.
__global__ __launch_bounds__(256) void perc_kernel(const float *__restrict__ S,
                                                   const float *__restrict__ H,
                                                   float *__restrict__ o1,
                                                   float *__restrict__ o2) {
    const int col = blockIdx.x * 256 + threadIdx.x;  // 0..1023
    const int g = blockIdx.y;                        // 0..256 (257 groups, last partial)
    const int img = blockIdx.z;                      // 0..3
    const float *Sp = S + (size_t)img * HH * WW;
    const int r0 = g * 4 - HALF;

    float x[34];
#pragma unroll
    for (int k = 0; k < 34; ++k) {
        int r = r0 + k;
        x[k] = (r >= 0 && r < HH) ? Sp[(size_t)r * WW + col] : 0.0f;
    }

    float c[28];
#pragma unroll
    for (int i = 0; i < 28; ++i) c[i] = x[3 + i];
    bsort<28>(c);

    float m[4];
    m[0] = med31(c, x[0], x[1], x[2]);
    m[1] = med31(c, x[1], x[2], x[31]);
    m[2] = med31(c, x[2], x[31], x[32]);
    m[3] = med31(c, x[31], x[32], x[33]);

#pragma unroll
    for (int i = 0; i < 4; ++i) {
        int r = g * 4 + i;
        if (r < HH) {
            size_t idx = (size_t)img * HH * WW + (size_t)r * WW + col;
            float s = x[i + HALF];  // S at the output location
            float h = H[idx];
            float p = m[i];
            float Z = fmaxf(h, p);
            if (Z < 1.17549435e-38f) Z = 1.0f;
            float zi = 1.0f / Z;
            float a = h * zi;
            float b = p * zi;
            float a2 = a * a;
            float b2 = b * b;
            float di = 1.0f / (a2 + b2);
            o1[idx] = s * (a2 * di);
            o2[idx] = s * (b2 * di);
        }
    }
}

extern "C" void kernel_launch(void *const *d_in, const int *in_sizes, int n_in,
                              void *d_out, int out_size) {
    const float *S = (const float *)d_in[0];
    float *out = (float *)d_out;
    float *o1 = out;          // S * mask_harm
    float *o2 = out + NTOT;   // S * mask_perc

    float *H;
    cudaGetSymbolAddress((void **)&H, g_harm);

    // 4100 rows, one block each
    harm_kernel<<<NIMG * HH, 256>>>(S, H);

    dim3 grid(WW / 256, (HH + 3) / 4, NIMG);  // (4, 257, 4)
    perc_kernel<<<grid, 256>>>(S, H, o1, o2);
}

// round 2
// speedup vs baseline: 1.5313x; 1.5313x over previous
#include <cuda_runtime.h>
#include <stdint.h>

// HPSS: harm = median_31 along W, perc = median_31 along H (zero-padded),
// then soft masks m = x^2/(h^2+p^2); out = concat(S*m_h, S*m_p).
// S: (2,2,1025,1024) fp32 -> 4 images of 1025x1024.

#define HALF 15
#define NIMG 4
#define HH 1025
#define WW 1024
#define NTOT (NIMG * HH * WW)   // 4,198,400

// scratch for harmonic median (alloc-free rule: __device__ global)
__device__ float g_harm[NTOT];

__device__ __forceinline__ void ce(float &a, float &b) {
    float lo = fminf(a, b);
    float hi = fmaxf(a, b);
    a = lo;
    b = hi;
}

// Batcher odd-even mergesort for arbitrary N (out-of-range comparators dropped
// == +inf padding). Fully unrolled -> register-resident when regs suffice.
template <int N>
__device__ __forceinline__ void bsort(float *a) {
#pragma unroll
    for (int p = 1; p < N; p <<= 1) {
#pragma unroll
        for (int k = p; k >= 1; k >>= 1) {
#pragma unroll
            for (int j = k % p; j + k < N; j += 2 * k) {
#pragma unroll
                for (int i = 0; i < k; ++i) {
                    if (i + j + k < N) {
                        if ((i + j) / (2 * p) == (i + j + k) / (2 * p)) {
                            ce(a[i + j], a[i + j + k]);
                        }
                    }
                }
            }
        }
    }
}

// median of 31 = rank-3 of {core ranks 12..15, 3 extras}.
__device__ __forceinline__ float med31(const float *c, float e0, float e1, float e2) {
    float v[7] = {c[12], c[13], c[14], c[15], e0, e1, e2};
    bsort<7>(v);
    return v[3];
}

// ---------------- harmonic: median along W ----------------
// One block per row; row staged in smem with zero pads. Each thread computes
// 4 consecutive outputs: sort the shared 28-core once, re-read the 6 extras
// from smem afterwards (keeps live registers ~= c[28] only).
__global__ __launch_bounds__(256, 2) void harm_kernel(const float *__restrict__ S,
                                                      float *__restrict__ H) {
    __shared__ __align__(16) float sm[HALF + WW + HALF + 10];  // 1064 floats
    const int row = blockIdx.x;  // 0..4099
    const float *rp = S + (size_t)row * WW;
    const int t = threadIdx.x;

    if (t < HALF) sm[t] = 0.0f;
    if (t < HALF + 10) sm[HALF + WW + t] = 0.0f;
#pragma unroll
    for (int i = 0; i < 4; ++i) sm[HALF + t + 256 * i] = rp[t + 256 * i];
    __syncthreads();

    const float *w = &sm[4 * t];  // window base: outputs 4t..4t+3 use w[0..33]

    float c[28];
#pragma unroll
    for (int i = 0; i < 28; ++i) c[i] = w[3 + i];
    bsort<28>(c);

    // extras re-read from smem AFTER the sort (cheap, keeps reg pressure low)
    float e0 = w[0], e1 = w[1], e2 = w[2];
    float f0 = w[31], f1 = w[32], f2 = w[33];

    float m0 = med31(c, e0, e1, e2);
    float m1 = med31(c, e1, e2, f0);
    float m2 = med31(c, e2, f0, f1);
    float m3 = med31(c, f0, f1, f2);

    float4 *hp = (float4 *)(H + (size_t)row * WW + 4 * t);
    *hp = make_float4(m0, m1, m2, m3);
}

// ------- percussive: median along H + fused softmask/outputs -------
// threadIdx.x = column (coalesced). Each thread: 4 consecutive-row outputs.
// Core of 28 built directly from gmem; extras + S re-read afterwards (L1/L2 hit).
__global__ __launch_bounds__(256, 2) void perc_kernel(const float *__restrict__ S,
                                                      const float *__restrict__ H,
                                                      float *__restrict__ o1,
                                                      float *__restrict__ o2) {
    const int col = blockIdx.x * 256 + threadIdx.x;  // 0..1023
    const int g = blockIdx.y;                        // 0..256
    const int img = blockIdx.z;                      // 0..3
    const float *Sp = S + (size_t)img * HH * WW + col;
    const int r0 = g * 4 - HALF;

    // core rows r0+3 .. r0+30
    float c[28];
#pragma unroll
    for (int i = 0; i < 28; ++i) {
        int r = r0 + 3 + i;
        c[i] = (r >= 0 && r < HH) ? Sp[(size_t)r * WW] : 0.0f;
    }
    bsort<28>(c);

    // extras (rows r0, r0+1, r0+2, r0+31, r0+32, r0+33), re-read after sort
    float ex[6];
#pragma unroll
    for (int i = 0; i < 3; ++i) {
        int r = r0 + i;
        ex[i] = (r >= 0 && r < HH) ? Sp[(size_t)r * WW] : 0.0f;
    }
#pragma unroll
    for (int i = 0; i < 3; ++i) {
        int r = r0 + 31 + i;
        ex[3 + i] = (r >= 0 && r < HH) ? Sp[(size_t)r * WW] : 0.0f;
    }

    float m[4];
    m[0] = med31(c, ex[0], ex[1], ex[2]);
    m[1] = med31(c, ex[1], ex[2], ex[3]);
    m[2] = med31(c, ex[2], ex[3], ex[4]);
    m[3] = med31(c, ex[3], ex[4], ex[5]);

#pragma unroll
    for (int i = 0; i < 4; ++i) {
        int r = g * 4 + i;
        if (r < HH) {
            size_t idx = (size_t)img * HH * WW + (size_t)r * WW + col;
            float s = Sp[(size_t)r * WW];  // L1/L2 hit (loaded during core build)
            float h = H[idx];
            float p = m[i];
            float Z = fmaxf(h, p);
            if (Z < 1.17549435e-38f) Z = 1.0f;
            float zi = 1.0f / Z;
            float a = h * zi;
            float b = p * zi;
            float a2 = a * a;
            float b2 = b * b;
            float di = 1.0f / (a2 + b2);
            o1[idx] = s * (a2 * di);
            o2[idx] = s * (b2 * di);
        }
    }
}

extern "C" void kernel_launch(void *const *d_in, const int *in_sizes, int n_in,
                              void *d_out, int out_size) {
    const float *S = (const float *)d_in[0];
    float *out = (float *)d_out;
    float *o1 = out;          // S * mask_harm
    float *o2 = out + NTOT;   // S * mask_perc

    float *H;
    cudaGetSymbolAddress((void **)&H, g_harm);

    harm_kernel<<<NIMG * HH, 256>>>(S, H);

    dim3 grid(WW / 256, (HH + 3) / 4, NIMG);  // (4, 257, 4)
    perc_kernel<<<grid, 256>>>(S, H, o1, o2);
}

// round 3
// speedup vs baseline: 5.9361x; 3.8765x over previous
#include <cuda_runtime.h>
#include <stdint.h>

// HPSS: harm = median_31 along W, perc = median_31 along H (zero-padded),
// soft masks m = x^2/(h^2+p^2); out = concat(S*m_h, S*m_p).
// S: (2,2,1025,1024) fp32 -> 4 images of 1025x1024.

#define HALF 15
#define NIMG 4
#define HH 1025
#define WW 1024
#define NTOT (NIMG * HH * WW)   // 4,198,400

// scratch for harmonic median (alloc-free rule: __device__ global)
__device__ float g_harm[NTOT];

__device__ __forceinline__ void ce(float &a, float &b) {
    float lo = fminf(a, b);
    float hi = fmaxf(a, b);
    a = lo;
    b = hi;
}

// ---- compile-time Batcher odd-even mergesort network ----
// The CE pair list is built by a constexpr function and applied via
// if-constexpr recursion: every array index is a constexpr int, so the
// float arrays CANNOT be dynamically indexed -> guaranteed register residency
// (this was the Round-1/2 bug: pragma-unroll nest left dynamic indexing ->
// arrays in local memory -> L1=79% on LDL/STL).

template <int N>
constexpr int count_pairs() {
    int c = 0;
    for (int p = 1; p < N; p <<= 1)
        for (int k = p; k >= 1; k >>= 1)
            for (int j = k % p; j + k < N; j += 2 * k)
                for (int i = 0; i < k; ++i)
                    if (i + j + k < N && (i + j) / (2 * p) == (i + j + k) / (2 * p)) ++c;
    return c;
}

template <int M>
struct PairList {
    int a[M];
    int b[M];
};

template <int N, int M>
constexpr PairList<M> make_pairs() {
    PairList<M> L{};
    int c = 0;
    for (int p = 1; p < N; p <<= 1)
        for (int k = p; k >= 1; k >>= 1)
            for (int j = k % p; j + k < N; j += 2 * k)
                for (int i = 0; i < k; ++i)
                    if (i + j + k < N && (i + j) / (2 * p) == (i + j + k) / (2 * p)) {
                        L.a[c] = i + j;
                        L.b[c] = i + j + k;
                        ++c;
                    }
    return L;
}

template <int N>
struct Net {
    static constexpr int M = count_pairs<N>();
    static constexpr PairList<M> L = make_pairs<N, M>();

    template <int I = 0>
    static __device__ __forceinline__ void run(float (&x)[N]) {
        if constexpr (I < M) {
            constexpr int ia = L.a[I];
            constexpr int ib = L.b[I];
            ce(x[ia], x[ib]);
            run<I + 1>(x);
        }
    }
};

// median of 31 = rank-3 of {core ranks 12..15, 3 extras}
__device__ __forceinline__ float med31(const float (&c)[28], float e0, float e1, float e2) {
    float v[7] = {c[12], c[13], c[14], c[15], e0, e1, e2};
    Net<7>::run(v);
    return v[3];
}

// ---------------- harmonic: median along W ----------------
__global__ __launch_bounds__(256, 2) void harm_kernel(const float *__restrict__ S,
                                                      float *__restrict__ H) {
    __shared__ __align__(16) float sm[HALF + WW + HALF + 10];  // 1064 floats
    const int row = blockIdx.x;  // 0..4099
    const float *rp = S + (size_t)row * WW;
    const int t = threadIdx.x;

    if (t < HALF) sm[t] = 0.0f;
    if (t < HALF + 10) sm[HALF + WW + t] = 0.0f;
#pragma unroll
    for (int i = 0; i < 4; ++i) sm[HALF + t + 256 * i] = rp[t + 256 * i];
    __syncthreads();

    const float *w = &sm[4 * t];  // outputs 4t..4t+3 use w[0..33]

    float c[28];
#pragma unroll
    for (int i = 0; i < 28; ++i) c[i] = w[3 + i];
    Net<28>::run(c);

    // extras re-read from smem after the sort (keeps reg pressure low)
    float e0 = w[0], e1 = w[1], e2 = w[2];
    float f0 = w[31], f1 = w[32], f2 = w[33];

    float m0 = med31(c, e0, e1, e2);
    float m1 = med31(c, e1, e2, f0);
    float m2 = med31(c, e2, f0, f1);
    float m3 = med31(c, f0, f1, f2);

    float4 *hp = (float4 *)(H + (size_t)row * WW + 4 * t);
    *hp = make_float4(m0, m1, m2, m3);
}

// ------- percussive: median along H + fused softmask/outputs -------
__global__ __launch_bounds__(256, 2) void perc_kernel(const float *__restrict__ S,
                                                      const float *__restrict__ H,
                                                      float *__restrict__ o1,
                                                      float *__restrict__ o2) {
    const int col = blockIdx.x * 256 + threadIdx.x;  // 0..1023
    const int g = blockIdx.y;                        // 0..256
    const int img = blockIdx.z;                      // 0..3
    const float *Sp = S + (size_t)img * HH * WW + col;
    const int r0 = g * 4 - HALF;

    float c[28];
#pragma unroll
    for (int i = 0; i < 28; ++i) {
        int r = r0 + 3 + i;
        c[i] = (r >= 0 && r < HH) ? Sp[(size_t)r * WW] : 0.0f;
    }
    Net<28>::run(c);

    float ex[6];
#pragma unroll
    for (int i = 0; i < 3; ++i) {
        int r = r0 + i;
        ex[i] = (r >= 0 && r < HH) ? Sp[(size_t)r * WW] : 0.0f;
    }
#pragma unroll
    for (int i = 0; i < 3; ++i) {
        int r = r0 + 31 + i;
        ex[3 + i] = (r >= 0 && r < HH) ? Sp[(size_t)r * WW] : 0.0f;
    }

    float m[4];
    m[0] = med31(c, ex[0], ex[1], ex[2]);
    m[1] = med31(c, ex[1], ex[2], ex[3]);
    m[2] = med31(c, ex[2], ex[3], ex[4]);
    m[3] = med31(c, ex[3], ex[4], ex[5]);

#pragma unroll
    for (int i = 0; i < 4; ++i) {
        int r = g * 4 + i;
        if (r < HH) {
            size_t idx = (size_t)img * HH * WW + (size_t)r * WW + col;
            float s = Sp[(size_t)r * WW];  // L1 hit (loaded during core build)
            float h = H[idx];
            float p = m[i];
            float Z = fmaxf(h, p);
            if (Z < 1.17549435e-38f) Z = 1.0f;
            float zi = 1.0f / Z;
            float a = h * zi;
            float b = p * zi;
            float a2 = a * a;
            float b2 = b * b;
            float di = 1.0f / (a2 + b2);
            o1[idx] = s * (a2 * di);
            o2[idx] = s * (b2 * di);
        }
    }
}

extern "C" void kernel_launch(void *const *d_in, const int *in_sizes, int n_in,
                              void *d_out, int out_size) {
    const float *S = (const float *)d_in[0];
    float *out = (float *)d_out;
    float *o1 = out;          // S * mask_harm
    float *o2 = out + NTOT;   // S * mask_perc

    float *H;
    cudaGetSymbolAddress((void **)&H, g_harm);

    harm_kernel<<<NIMG * HH, 256>>>(S, H);

    dim3 grid(WW / 256, (HH + 3) / 4, NIMG);  // (4, 257, 4)
    perc_kernel<<<grid, 256>>>(S, H, o1, o2);
}

// round 4
// speedup vs baseline: 6.7871x; 1.1434x over previous
#include <cuda_runtime.h>
#include <stdint.h>

// HPSS: harm = median_31 along W, perc = median_31 along H (zero-padded),
// soft masks m = x^2/(h^2+p^2); out = concat(S*m_h, S*m_p).
// S: (2,2,1025,1024) fp32 -> 4 images of 1025x1024.

#define HALF 15
#define NIMG 4
#define HH 1025
#define WW 1024
#define NTOT (NIMG * HH * WW)   // 4,198,400

__device__ float g_harm[NTOT];  // scratch (alloc-free rule)

__device__ __forceinline__ void ce(float &a, float &b) {
    float lo = fminf(a, b);
    float hi = fmaxf(a, b);
    a = lo;
    b = hi;
}

// ---- compile-time Batcher network, pruned to a rank range ----
template <int N>
constexpr int count_pairs() {
    int c = 0;
    for (int p = 1; p < N; p <<= 1)
        for (int k = p; k >= 1; k >>= 1)
            for (int j = k % p; j + k < N; j += 2 * k)
                for (int i = 0; i < k; ++i)
                    if (i + j + k < N && (i + j) / (2 * p) == (i + j + k) / (2 * p)) ++c;
    return c;
}

template <int M>
struct PairList {
    int a[M];
    int b[M];
};

template <int N, int M>
constexpr PairList<M> make_pairs() {
    PairList<M> L{};
    int c = 0;
    for (int p = 1; p < N; p <<= 1)
        for (int k = p; k >= 1; k >>= 1)
            for (int j = k % p; j + k < N; j += 2 * k)
                for (int i = 0; i < k; ++i)
                    if (i + j + k < N && (i + j) / (2 * p) == (i + j + k) / (2 * p)) {
                        L.a[c] = i + j;
                        L.b[c] = i + j + k;
                        ++c;
                    }
    return L;
}

// Backward dependency pruning: outputs outside [LO,HI] are never read, so a
// comparator is kept only if one of its wires is still needed downstream.
template <int N, int M>
constexpr int count_kept(const PairList<M> &L, int lo, int hi) {
    bool need[64] = {};
    for (int i = lo; i <= hi; ++i) need[i] = true;
    int cnt = 0;
    for (int t = M - 1; t >= 0; --t)
        if (need[L.a[t]] || need[L.b[t]]) {
            ++cnt;
            need[L.a[t]] = true;
            need[L.b[t]] = true;
        }
    return cnt;
}

template <int N, int M, int MK>
constexpr PairList<MK> prune_pairs(const PairList<M> &L, int lo, int hi) {
    bool need[64] = {};
    bool keep[512] = {};
    for (int i = lo; i <= hi; ++i) need[i] = true;
    for (int t = M - 1; t >= 0; --t)
        if (need[L.a[t]] || need[L.b[t]]) {
            keep[t] = true;
            need[L.a[t]] = true;
            need[L.b[t]] = true;
        }
    PairList<MK> R{};
    int c = 0;
    for (int t = 0; t < M; ++t)
        if (keep[t]) {
            R.a[c] = L.a[t];
            R.b[c] = L.b[t];
            ++c;
        }
    return R;
}

template <int N, int LO, int HI>
struct SelNet {
    static constexpr int M = count_pairs<N>();
    static constexpr PairList<M> Lf = make_pairs<N, M>();
    static constexpr int MK = count_kept<N, M>(Lf, LO, HI);
    static constexpr PairList<MK> L = prune_pairs<N, M, MK>(Lf, LO, HI);

    template <int I = 0>
    static __device__ __forceinline__ void run(float (&x)[N]) {
        if constexpr (I < MK) {
            constexpr int ia = L.a[I];
            constexpr int ib = L.b[I];
            ce(x[ia], x[ib]);
            run<I + 1>(x);
        }
    }
};

// rank-3 of union(sorted A=(c12..c15), sorted B=(b0,b1,b2)):
// x_3 = max over i+j=3 of min(A_i, B_j), out-of-range -> +inf.
__device__ __forceinline__ float sel3(const float (&c)[28], float b0, float b1, float b2) {
    float t1 = fminf(c[13], b2);
    float t2 = fminf(c[14], b1);
    float t3 = fminf(c[15], b0);
    return fmaxf(fmaxf(c[12], t1), fmaxf(t2, t3));
}

// Four medians from sorted core c (ranks 12..15 valid) and six raw extras
// e0..e5 (windows slide: {e0,e1,e2},{e1,e2,e3},{e2,e3,e4},{e3,e4,e5}).
// Shared pair-sorts + 2-CE inserts: 10 CE total, then 6-op selects.
__device__ __forceinline__ void four_medians(const float (&c)[28], float e0, float e1,
                                             float e2, float e3, float e4, float e5,
                                             float &m0, float &m1, float &m2, float &m3) {
    float l12 = fminf(e1, e2), h12 = fmaxf(e1, e2);
    float l34 = fminf(e3, e4), h34 = fmaxf(e3, e4);

    // {e0, l12, h12}
    {
        float a = fminf(e0, l12), t = fmaxf(e0, l12);
        float b = fminf(t, h12), d = fmaxf(t, h12);
        m0 = sel3(c, a, b, d);
    }
    // {l12, h12, e3}
    {
        float t = fminf(h12, e3), T = fmaxf(h12, e3);
        float a = fminf(l12, t), b = fmaxf(l12, t);
        m1 = sel3(c, a, b, T);
    }
    // {e2, l34, h34}
    {
        float a = fminf(e2, l34), t = fmaxf(e2, l34);
        float b = fminf(t, h34), d = fmaxf(t, h34);
        m2 = sel3(c, a, b, d);
    }
    // {l34, h34, e5}
    {
        float t = fminf(h34, e5), T = fmaxf(h34, e5);
        float a = fminf(l34, t), b = fmaxf(l34, t);
        m3 = sel3(c, a, b, T);
    }
}

// ---------------- harmonic: median along W ----------------
__global__ __launch_bounds__(256, 2) void harm_kernel(const float *__restrict__ S,
                                                      float *__restrict__ H) {
    __shared__ __align__(16) float sm[HALF + WW + HALF + 10];  // 1064 floats
    const int row = blockIdx.x;  // 0..4099
    const float *rp = S + (size_t)row * WW;
    const int t = threadIdx.x;

    if (t < HALF) sm[t] = 0.0f;
    if (t < HALF + 10) sm[HALF + WW + t] = 0.0f;
#pragma unroll
    for (int i = 0; i < 4; ++i) sm[HALF + t + 256 * i] = rp[t + 256 * i];
    __syncthreads();

    const float *w = &sm[4 * t];  // outputs 4t..4t+3 use w[0..33]

    float c[28];
#pragma unroll
    for (int i = 0; i < 28; ++i) c[i] = w[3 + i];
    SelNet<28, 12, 15>::run(c);

    float m0, m1, m2, m3;
    four_medians(c, w[0], w[1], w[2], w[31], w[32], w[33], m0, m1, m2, m3);

    float4 *hp = (float4 *)(H + (size_t)row * WW + 4 * t);
    *hp = make_float4(m0, m1, m2, m3);
}

// ------- percussive: median along H + fused softmask/outputs -------
__global__ __launch_bounds__(256, 2) void perc_kernel(const float *__restrict__ S,
                                                      const float *__restrict__ H,
                                                      float *__restrict__ o1,
                                                      float *__restrict__ o2) {
    const int col = blockIdx.x * 256 + threadIdx.x;  // 0..1023
    const int g = blockIdx.y;                        // 0..256
    const int img = blockIdx.z;                      // 0..3
    const float *Sp = S + (size_t)img * HH * WW + col;
    const int r0 = g * 4 - HALF;

    float c[28];
#pragma unroll
    for (int i = 0; i < 28; ++i) {
        int r = r0 + 3 + i;
        c[i] = (r >= 0 && r < HH) ? Sp[(size_t)r * WW] : 0.0f;
    }
    SelNet<28, 12, 15>::run(c);

    float ex[6];
#pragma unroll
    for (int i = 0; i < 3; ++i) {
        int r = r0 + i;
        ex[i] = (r >= 0 && r < HH) ? Sp[(size_t)r * WW] : 0.0f;
    }
#pragma unroll
    for (int i = 0; i < 3; ++i) {
        int r = r0 + 31 + i;
        ex[3 + i] = (r >= 0 && r < HH) ? Sp[(size_t)r * WW] : 0.0f;
    }

    float m[4];
    four_medians(c, ex[0], ex[1], ex[2], ex[3], ex[4], ex[5], m[0], m[1], m[2], m[3]);

#pragma unroll
    for (int i = 0; i < 4; ++i) {
        int r = g * 4 + i;
        if (r < HH) {
            size_t idx = (size_t)img * HH * WW + (size_t)r * WW + col;
            float s = Sp[(size_t)r * WW];  // L1 hit (loaded during core build)
            float h = H[idx];
            float p = m[i];
            float Z = fmaxf(h, p);
            if (Z < 1.17549435e-38f) Z = 1.0f;
            float zi = 1.0f / Z;
            float a = h * zi;
            float b = p * zi;
            float a2 = a * a;
            float b2 = b * b;
            float di = 1.0f / (a2 + b2);
            o1[idx] = s * (a2 * di);
            o2[idx] = s * (b2 * di);
        }
    }
}

extern "C" void kernel_launch(void *const *d_in, const int *in_sizes, int n_in,
                              void *d_out, int out_size) {
    const float *S = (const float *)d_in[0];
    float *out = (float *)d_out;
    float *o1 = out;          // S * mask_harm
    float *o2 = out + NTOT;   // S * mask_perc

    float *H;
    cudaGetSymbolAddress((void **)&H, g_harm);

    harm_kernel<<<NIMG * HH, 256>>>(S, H);

    dim3 grid(WW / 256, (HH + 3) / 4, NIMG);  // (4, 257, 4)
    perc_kernel<<<grid, 256>>>(S, H, o1, o2);
}

// round 5
// speedup vs baseline: 7.5690x; 1.1152x over previous
#include <cuda_runtime.h>
#include <cuda_fp16.h>
#include <stdint.h>

// HPSS: harm = median_31 along W, perc = median_31 along H (zero-padded),
// soft masks m = x^2/(h^2+p^2); out = concat(S*m_h, S*m_p).
// S: (2,2,1025,1024) fp32 -> 4 images of 1025x1024.
// Medians computed in fp16x2 (HMNMX2: 2 lanes per alu op); masks in fp32.

#define HALF 15
#define NIMG 4
#define HH 1025
#define WW 1024
#define NTOT (NIMG * HH * WW)   // 4,198,400

__device__ __half g_harm[NTOT];  // harmonic median scratch (fp16)

__device__ __forceinline__ void ce2(__half2 &a, __half2 &b) {
    __half2 lo = __hmin2(a, b);
    __half2 hi = __hmax2(a, b);
    a = lo;
    b = hi;
}

// ---- compile-time Batcher network, pruned to a rank range ----
template <int N>
constexpr int count_pairs() {
    int c = 0;
    for (int p = 1; p < N; p <<= 1)
        for (int k = p; k >= 1; k >>= 1)
            for (int j = k % p; j + k < N; j += 2 * k)
                for (int i = 0; i < k; ++i)
                    if (i + j + k < N && (i + j) / (2 * p) == (i + j + k) / (2 * p)) ++c;
    return c;
}

template <int M>
struct PairList {
    int a[M];
    int b[M];
};

template <int N, int M>
constexpr PairList<M> make_pairs() {
    PairList<M> L{};
    int c = 0;
    for (int p = 1; p < N; p <<= 1)
        for (int k = p; k >= 1; k >>= 1)
            for (int j = k % p; j + k < N; j += 2 * k)
                for (int i = 0; i < k; ++i)
                    if (i + j + k < N && (i + j) / (2 * p) == (i + j + k) / (2 * p)) {
                        L.a[c] = i + j;
                        L.b[c] = i + j + k;
                        ++c;
                    }
    return L;
}

template <int N, int M>
constexpr int count_kept(const PairList<M> &L, int lo, int hi) {
    bool need[64] = {};
    for (int i = lo; i <= hi; ++i) need[i] = true;
    int cnt = 0;
    for (int t = M - 1; t >= 0; --t)
        if (need[L.a[t]] || need[L.b[t]]) {
            ++cnt;
            need[L.a[t]] = true;
            need[L.b[t]] = true;
        }
    return cnt;
}

template <int N, int M, int MK>
constexpr PairList<MK> prune_pairs(const PairList<M> &L, int lo, int hi) {
    bool need[64] = {};
    bool keep[512] = {};
    for (int i = lo; i <= hi; ++i) need[i] = true;
    for (int t = M - 1; t >= 0; --t)
        if (need[L.a[t]] || need[L.b[t]]) {
            keep[t] = true;
            need[L.a[t]] = true;
            need[L.b[t]] = true;
        }
    PairList<MK> R{};
    int c = 0;
    for (int t = 0; t < M; ++t)
        if (keep[t]) {
            R.a[c] = L.a[t];
            R.b[c] = L.b[t];
            ++c;
        }
    return R;
}

template <int N, int LO, int HI>
struct SelNet {
    static constexpr int M = count_pairs<N>();
    static constexpr PairList<M> Lf = make_pairs<N, M>();
    static constexpr int MK = count_kept<N, M>(Lf, LO, HI);
    static constexpr PairList<MK> L = prune_pairs<N, M, MK>(Lf, LO, HI);

    template <int I = 0>
    static __device__ __forceinline__ void run(__half2 (&x)[N]) {
        if constexpr (I < MK) {
            constexpr int ia = L.a[I];
            constexpr int ib = L.b[I];
            ce2(x[ia], x[ib]);
            run<I + 1>(x);
        }
    }
};

// rank-3 of union(sorted A=(c12..c15), sorted B=(b0<=b1<=b2)), per lane
__device__ __forceinline__ __half2 sel3(const __half2 (&c)[28], __half2 b0, __half2 b1,
                                        __half2 b2) {
    __half2 t1 = __hmin2(c[13], b2);
    __half2 t2 = __hmin2(c[14], b1);
    __half2 t3 = __hmin2(c[15], b0);
    return __hmax2(__hmax2(c[12], t1), __hmax2(t2, t3));
}

// Four medians from sorted core c (ranks 12..15 valid) and six raw extras.
// Sliding windows {e0,e1,e2},{e1,e2,e3},{e2,e3,e4},{e3,e4,e5}.
__device__ __forceinline__ void four_medians(const __half2 (&c)[28], __half2 e0, __half2 e1,
                                             __half2 e2, __half2 e3, __half2 e4, __half2 e5,
                                             __half2 &m0, __half2 &m1, __half2 &m2,
                                             __half2 &m3) {
    __half2 l12 = __hmin2(e1, e2), h12 = __hmax2(e1, e2);
    __half2 l34 = __hmin2(e3, e4), h34 = __hmax2(e3, e4);
    {
        __half2 a = __hmin2(e0, l12), t = __hmax2(e0, l12);
        __half2 b = __hmin2(t, h12), d = __hmax2(t, h12);
        m0 = sel3(c, a, b, d);
    }
    {
        __half2 t = __hmin2(h12, e3), T = __hmax2(h12, e3);
        __half2 a = __hmin2(l12, t), b = __hmax2(l12, t);
        m1 = sel3(c, a, b, T);
    }
    {
        __half2 a = __hmin2(e2, l34), t = __hmax2(e2, l34);
        __half2 b = __hmin2(t, h34), d = __hmax2(t, h34);
        m2 = sel3(c, a, b, d);
    }
    {
        __half2 t = __hmin2(h34, e5), T = __hmax2(h34, e5);
        __half2 a = __hmin2(l34, t), b = __hmax2(l34, t);
        m3 = sel3(c, a, b, T);
    }
}

// ---------------- harmonic: median along W, 2 rows per half2 lane ----------------
__global__ __launch_bounds__(256, 2) void harm_kernel(const float *__restrict__ S,
                                                      __half *__restrict__ H) {
    __shared__ __align__(16) __half2 sm[HALF + WW + HALF + 14];  // 1068 half2
    const int rp = blockIdx.x;  // row pair 0..2049 (rows independent; pairing ok)
    const float *r0p = S + (size_t)(2 * rp) * WW;
    const float *r1p = r0p + WW;
    const int t = threadIdx.x;

    const __half2 z2 = __float2half2_rn(0.0f);
    if (t < HALF) sm[t] = z2;
    if (t < HALF + 14) sm[HALF + WW + t] = z2;
#pragma unroll
    for (int i = 0; i < 4; ++i)
        sm[HALF + t + 256 * i] = __floats2half2_rn(r0p[t + 256 * i], r1p[t + 256 * i]);
    __syncthreads();

    // window: outputs cols 4t..4t+3 use sm[4t .. 4t+33] (+2 overread), 16B-aligned
    const uint4 *wv = reinterpret_cast<const uint4 *>(&sm[4 * t]);
    __half2 x[36];
#pragma unroll
    for (int q = 0; q < 9; ++q) {
        uint4 v = wv[q];
        x[4 * q + 0] = *reinterpret_cast<__half2 *>(&v.x);
        x[4 * q + 1] = *reinterpret_cast<__half2 *>(&v.y);
        x[4 * q + 2] = *reinterpret_cast<__half2 *>(&v.z);
        x[4 * q + 3] = *reinterpret_cast<__half2 *>(&v.w);
    }

    __half2 c[28];
#pragma unroll
    for (int i = 0; i < 28; ++i) c[i] = x[3 + i];
    SelNet<28, 12, 15>::run(c);

    __half2 m0, m1, m2, m3;
    four_medians(c, x[0], x[1], x[2], x[31], x[32], x[33], m0, m1, m2, m3);

    __half *h0 = H + (size_t)(2 * rp) * WW + 4 * t;
    __half *h1 = h0 + WW;
    h0[0] = __low2half(m0);  h1[0] = __high2half(m0);
    h0[1] = __low2half(m1);  h1[1] = __high2half(m1);
    h0[2] = __low2half(m2);  h1[2] = __high2half(m2);
    h0[3] = __low2half(m3);  h1[3] = __high2half(m3);
}

// ------- percussive: median along H, 2 cols per lane, fused softmask -------
template <bool GUARD>
__global__ __launch_bounds__(256, 2) void perc_kernel(const float *__restrict__ S,
                                                      const __half *__restrict__ H,
                                                      float *__restrict__ o1,
                                                      float *__restrict__ o2) {
    const int cp = blockIdx.x * 256 + threadIdx.x;  // column pair 0..511
    const int col = 2 * cp;
    int g;
    if (GUARD) {
        int gy = blockIdx.y;  // 0..8 -> groups {0..3, 252..256}
        g = (gy < 4) ? gy : (gy + 248);
    } else {
        g = blockIdx.y + 4;  // 4..251 (all rows in-bounds)
    }
    const int img = blockIdx.z;
    const float *Sp = S + (size_t)img * HH * WW + col;
    const int r0 = g * 4 - HALF;

    __half2 c[28];
    float2 smid[4];  // fp32 S at output rows (core positions 12..15)
#pragma unroll
    for (int i = 0; i < 28; ++i) {
        int r = r0 + 3 + i;
        float2 v;
        if (!GUARD || (r >= 0 && r < HH))
            v = *reinterpret_cast<const float2 *>(&Sp[(size_t)r * WW]);
        else
            v = make_float2(0.0f, 0.0f);
        if (i >= 12 && i < 16) smid[i - 12] = v;
        c[i] = __floats2half2_rn(v.x, v.y);
    }
    SelNet<28, 12, 15>::run(c);

    __half2 ex[6];
#pragma unroll
    for (int i = 0; i < 6; ++i) {
        int r = (i < 3) ? (r0 + i) : (r0 + 28 + i);  // r0,r0+1,r0+2, r0+31..r0+33
        float2 v;
        if (!GUARD || (r >= 0 && r < HH))
            v = *reinterpret_cast<const float2 *>(&Sp[(size_t)r * WW]);
        else
            v = make_float2(0.0f, 0.0f);
        ex[i] = __floats2half2_rn(v.x, v.y);
    }

    __half2 m[4];
    four_medians(c, ex[0], ex[1], ex[2], ex[3], ex[4], ex[5], m[0], m[1], m[2], m[3]);

#pragma unroll
    for (int i = 0; i < 4; ++i) {
        int r = g * 4 + i;
        if (!GUARD || r < HH) {
            size_t idx = (size_t)img * HH * WW + (size_t)r * WW + col;
            float2 s = smid[i];
            float2 hf = __half22float2(*reinterpret_cast<const __half2 *>(&H[idx]));
            float2 pf = __half22float2(m[i]);
            float2 r1, r2;
            {
                float h = hf.x, p = pf.x;
                float Z = fmaxf(h, p);
                if (Z < 1.17549435e-38f) Z = 1.0f;
                float zi = 1.0f / Z;
                float a = h * zi, b = p * zi;
                float a2 = a * a, b2 = b * b;
                float di = 1.0f / (a2 + b2);
                r1.x = s.x * (a2 * di);
                r2.x = s.x * (b2 * di);
            }
            {
                float h = hf.y, p = pf.y;
                float Z = fmaxf(h, p);
                if (Z < 1.17549435e-38f) Z = 1.0f;
                float zi = 1.0f / Z;
                float a = h * zi, b = p * zi;
                float a2 = a * a, b2 = b * b;
                float di = 1.0f / (a2 + b2);
                r1.y = s.y * (a2 * di);
                r2.y = s.y * (b2 * di);
            }
            *reinterpret_cast<float2 *>(&o1[idx]) = r1;
            *reinterpret_cast<float2 *>(&o2[idx]) = r2;
        }
    }
}

extern "C" void kernel_launch(void *const *d_in, const int *in_sizes, int n_in,
                              void *d_out, int out_size) {
    const float *S = (const float *)d_in[0];
    float *out = (float *)d_out;
    float *o1 = out;          // S * mask_harm
    float *o2 = out + NTOT;   // S * mask_perc

    __half *H;
    cudaGetSymbolAddress((void **)&H, g_harm);

    harm_kernel<<<NIMG * HH / 2, 256>>>(S, H);

    dim3 gi(2, 248, NIMG);  // interior groups 4..251, unguarded
    perc_kernel<false><<<gi, 256>>>(S, H, o1, o2);
    dim3 gb(2, 9, NIMG);    // boundary groups {0..3, 252..256}, guarded
    perc_kernel<true><<<gb, 256>>>(S, H, o1, o2);
}

// round 6
// speedup vs baseline: 7.6773x; 1.0143x over previous
#include <cuda_runtime.h>
#include <cuda_fp16.h>
#include <stdint.h>

// HPSS: harm = median_31 along W, perc = median_31 along H (zero-padded),
// soft masks m = x^2/(h^2+p^2); out = concat(S*m_h, S*m_p).
// S: (2,2,1025,1024) fp32 -> 4 images of 1025x1024.
// Medians in fp16, two lanes packed per 32-bit register; comparators are
// integer SIMD min.u16x2/max.u16x2 (exact for non-negative fp16: bit order
// == value order). Masks computed in fp32.

#define HALF 15
#define NIMG 4
#define HH 1025
#define WW 1024
#define NTOT (NIMG * HH * WW)   // 4,198,400

__device__ __half g_harm[NTOT];  // harmonic median scratch (fp16)

__device__ __forceinline__ uint32_t umin2(uint32_t a, uint32_t b) {
    uint32_t d;
    asm("min.u16x2 %0, %1, %2;" : "=r"(d) : "r"(a), "r"(b));
    return d;
}
__device__ __forceinline__ uint32_t umax2(uint32_t a, uint32_t b) {
    uint32_t d;
    asm("max.u16x2 %0, %1, %2;" : "=r"(d) : "r"(a), "r"(b));
    return d;
}
__device__ __forceinline__ void ce2(uint32_t &a, uint32_t &b) {
    uint32_t lo = umin2(a, b);
    uint32_t hi = umax2(a, b);
    a = lo;
    b = hi;
}

__device__ __forceinline__ uint32_t pack2(float x, float y) {
    __half2 h = __floats2half2_rn(x, y);
    return *reinterpret_cast<uint32_t *>(&h);
}
__device__ __forceinline__ float2 unpack2(uint32_t v) {
    __half2 h = *reinterpret_cast<__half2 *>(&v);
    return __half22float2(h);
}

// ---- compile-time Batcher network, pruned to a rank range ----
template <int N>
constexpr int count_pairs() {
    int c = 0;
    for (int p = 1; p < N; p <<= 1)
        for (int k = p; k >= 1; k >>= 1)
            for (int j = k % p; j + k < N; j += 2 * k)
                for (int i = 0; i < k; ++i)
                    if (i + j + k < N && (i + j) / (2 * p) == (i + j + k) / (2 * p)) ++c;
    return c;
}

template <int M>
struct PairList {
    int a[M];
    int b[M];
};

template <int N, int M>
constexpr PairList<M> make_pairs() {
    PairList<M> L{};
    int c = 0;
    for (int p = 1; p < N; p <<= 1)
        for (int k = p; k >= 1; k >>= 1)
            for (int j = k % p; j + k < N; j += 2 * k)
                for (int i = 0; i < k; ++i)
                    if (i + j + k < N && (i + j) / (2 * p) == (i + j + k) / (2 * p)) {
                        L.a[c] = i + j;
                        L.b[c] = i + j + k;
                        ++c;
                    }
    return L;
}

template <int N, int M>
constexpr int count_kept(const PairList<M> &L, int lo, int hi) {
    bool need[64] = {};
    for (int i = lo; i <= hi; ++i) need[i] = true;
    int cnt = 0;
    for (int t = M - 1; t >= 0; --t)
        if (need[L.a[t]] || need[L.b[t]]) {
            ++cnt;
            need[L.a[t]] = true;
            need[L.b[t]] = true;
        }
    return cnt;
}

template <int N, int M, int MK>
constexpr PairList<MK> prune_pairs(const PairList<M> &L, int lo, int hi) {
    bool need[64] = {};
    bool keep[512] = {};
    for (int i = lo; i <= hi; ++i) need[i] = true;
    for (int t = M - 1; t >= 0; --t)
        if (need[L.a[t]] || need[L.b[t]]) {
            keep[t] = true;
            need[L.a[t]] = true;
            need[L.b[t]] = true;
        }
    PairList<MK> R{};
    int c = 0;
    for (int t = 0; t < M; ++t)
        if (keep[t]) {
            R.a[c] = L.a[t];
            R.b[c] = L.b[t];
            ++c;
        }
    return R;
}

template <int N, int LO, int HI>
struct SelNet {
    static constexpr int M = count_pairs<N>();
    static constexpr PairList<M> Lf = make_pairs<N, M>();
    static constexpr int MK = count_kept<N, M>(Lf, LO, HI);
    static constexpr PairList<MK> L = prune_pairs<N, M, MK>(Lf, LO, HI);

    template <int I = 0>
    static __device__ __forceinline__ void run(uint32_t (&x)[N]) {
        if constexpr (I < MK) {
            constexpr int ia = L.a[I];
            constexpr int ib = L.b[I];
            ce2(x[ia], x[ib]);
            run<I + 1>(x);
        }
    }
};

// rank-3 of union(sorted A=(c12..c15), sorted B=(b0<=b1<=b2)), per lane
__device__ __forceinline__ uint32_t sel3(const uint32_t (&c)[28], uint32_t b0, uint32_t b1,
                                         uint32_t b2) {
    uint32_t t1 = umin2(c[13], b2);
    uint32_t t2 = umin2(c[14], b1);
    uint32_t t3 = umin2(c[15], b0);
    return umax2(umax2(c[12], t1), umax2(t2, t3));
}

// Four medians from sorted core c (ranks 12..15 valid) and six raw extras.
// Sliding windows {e0,e1,e2},{e1,e2,e3},{e2,e3,e4},{e3,e4,e5}.
__device__ __forceinline__ void four_medians(const uint32_t (&c)[28], uint32_t e0,
                                             uint32_t e1, uint32_t e2, uint32_t e3,
                                             uint32_t e4, uint32_t e5, uint32_t &m0,
                                             uint32_t &m1, uint32_t &m2, uint32_t &m3) {
    uint32_t l12 = umin2(e1, e2), h12 = umax2(e1, e2);
    uint32_t l34 = umin2(e3, e4), h34 = umax2(e3, e4);
    {
        uint32_t a = umin2(e0, l12), t = umax2(e0, l12);
        uint32_t b = umin2(t, h12), d = umax2(t, h12);
        m0 = sel3(c, a, b, d);
    }
    {
        uint32_t t = umin2(h12, e3), T = umax2(h12, e3);
        uint32_t a = umin2(l12, t), b = umax2(l12, t);
        m1 = sel3(c, a, b, T);
    }
    {
        uint32_t a = umin2(e2, l34), t = umax2(e2, l34);
        uint32_t b = umin2(t, h34), d = umax2(t, h34);
        m2 = sel3(c, a, b, d);
    }
    {
        uint32_t t = umin2(h34, e5), T = umax2(h34, e5);
        uint32_t a = umin2(l34, t), b = umax2(l34, t);
        m3 = sel3(c, a, b, T);
    }
}

// ---------------- harmonic: median along W, 2 rows per packed lane ----------------
__global__ __launch_bounds__(256, 2) void harm_kernel(const float *__restrict__ S,
                                                      __half *__restrict__ H) {
    __shared__ __align__(16) uint32_t sm[HALF + WW + HALF + 14];  // 1068 packed
    const int rp = blockIdx.x;  // row pair 0..2049
    const float *r0p = S + (size_t)(2 * rp) * WW;
    const float *r1p = r0p + WW;
    const int t = threadIdx.x;

    if (t < HALF) sm[t] = 0u;
    if (t < HALF + 14) sm[HALF + WW + t] = 0u;
#pragma unroll
    for (int i = 0; i < 4; ++i)
        sm[HALF + t + 256 * i] = pack2(r0p[t + 256 * i], r1p[t + 256 * i]);
    __syncthreads();

    // outputs cols 4t..4t+3 use sm[4t .. 4t+33] (+2 overread), 16B-aligned
    const uint4 *wv = reinterpret_cast<const uint4 *>(&sm[4 * t]);
    uint32_t x[36];
#pragma unroll
    for (int q = 0; q < 9; ++q) {
        uint4 v = wv[q];
        x[4 * q + 0] = v.x;
        x[4 * q + 1] = v.y;
        x[4 * q + 2] = v.z;
        x[4 * q + 3] = v.w;
    }

    uint32_t c[28];
#pragma unroll
    for (int i = 0; i < 28; ++i) c[i] = x[3 + i];
    SelNet<28, 12, 15>::run(c);

    uint32_t m0, m1, m2, m3;
    four_medians(c, x[0], x[1], x[2], x[31], x[32], x[33], m0, m1, m2, m3);

    // repack: row0 gets low halves, row1 gets high halves; 2x STG.64
    uint2 row0 = make_uint2(__byte_perm(m0, m1, 0x5410), __byte_perm(m2, m3, 0x5410));
    uint2 row1 = make_uint2(__byte_perm(m0, m1, 0x7632), __byte_perm(m2, m3, 0x7632));
    *reinterpret_cast<uint2 *>(H + (size_t)(2 * rp) * WW + 4 * t) = row0;
    *reinterpret_cast<uint2 *>(H + (size_t)(2 * rp + 1) * WW + 4 * t) = row1;
}

// ------- percussive: median along H, 2 cols per lane, fused softmask -------
template <bool GUARD>
__global__ __launch_bounds__(256, 2) void perc_kernel(const float *__restrict__ S,
                                                      const __half *__restrict__ H,
                                                      float *__restrict__ o1,
                                                      float *__restrict__ o2) {
    const int cp = blockIdx.x * 256 + threadIdx.x;  // column pair 0..511
    const int col = 2 * cp;
    int g;
    if (GUARD) {
        int gy = blockIdx.y;  // 0..8 -> groups {0..3, 252..256}
        g = (gy < 4) ? gy : (gy + 248);
    } else {
        g = blockIdx.y + 4;  // 4..251 (all rows in-bounds)
    }
    const int img = blockIdx.z;
    const float *Sp = S + (size_t)img * HH * WW + col;
    const int r0 = g * 4 - HALF;

    uint32_t c[28];
    float2 smid[4];  // fp32 S at the 4 output rows (core positions 12..15)
#pragma unroll
    for (int i = 0; i < 28; ++i) {
        int r = r0 + 3 + i;
        float2 v;
        if (!GUARD || (r >= 0 && r < HH))
            v = *reinterpret_cast<const float2 *>(&Sp[(size_t)r * WW]);
        else
            v = make_float2(0.0f, 0.0f);
        if (i >= 12 && i < 16) smid[i - 12] = v;
        c[i] = pack2(v.x, v.y);
    }
    SelNet<28, 12, 15>::run(c);

    uint32_t ex[6];
#pragma unroll
    for (int i = 0; i < 6; ++i) {
        int r = (i < 3) ? (r0 + i) : (r0 + 28 + i);  // r0..r0+2, r0+31..r0+33
        float2 v;
        if (!GUARD || (r >= 0 && r < HH))
            v = *reinterpret_cast<const float2 *>(&Sp[(size_t)r * WW]);
        else
            v = make_float2(0.0f, 0.0f);
        ex[i] = pack2(v.x, v.y);
    }

    uint32_t m[4];
    four_medians(c, ex[0], ex[1], ex[2], ex[3], ex[4], ex[5], m[0], m[1], m[2], m[3]);

#pragma unroll
    for (int i = 0; i < 4; ++i) {
        int r = g * 4 + i;
        if (!GUARD || r < HH) {
            size_t idx = (size_t)img * HH * WW + (size_t)r * WW + col;
            float2 s = smid[i];
            float2 hf = unpack2(*reinterpret_cast<const uint32_t *>(&H[idx]));
            float2 pf = unpack2(m[i]);
            float2 r1, r2;
            {
                float h = hf.x, p = pf.x;
                float Z = fmaxf(h, p);
                if (Z < 1.17549435e-38f) Z = 1.0f;
                float zi = 1.0f / Z;
                float a = h * zi, b = p * zi;
                float a2 = a * a, b2 = b * b;
                float di = 1.0f / (a2 + b2);
                r1.x = s.x * (a2 * di);
                r2.x = s.x * (b2 * di);
            }
            {
                float h = hf.y, p = pf.y;
                float Z = fmaxf(h, p);
                if (Z < 1.17549435e-38f) Z = 1.0f;
                float zi = 1.0f / Z;
                float a = h * zi, b = p * zi;
                float a2 = a * a, b2 = b * b;
                float di = 1.0f / (a2 + b2);
                r1.y = s.y * (a2 * di);
                r2.y = s.y * (b2 * di);
            }
            *reinterpret_cast<float2 *>(&o1[idx]) = r1;
            *reinterpret_cast<float2 *>(&o2[idx]) = r2;
        }
    }
}

extern "C" void kernel_launch(void *const *d_in, const int *in_sizes, int n_in,
                              void *d_out, int out_size) {
    const float *S = (const float *)d_in[0];
    float *out = (float *)d_out;
    float *o1 = out;          // S * mask_harm
    float *o2 = out + NTOT;   // S * mask_perc

    __half *H;
    cudaGetSymbolAddress((void **)&H, g_harm);

    harm_kernel<<<NIMG * HH / 2, 256>>>(S, H);

    dim3 gi(2, 248, NIMG);  // interior groups 4..251, unguarded
    perc_kernel<false><<<gi, 256>>>(S, H, o1, o2);
    dim3 gb(2, 9, NIMG);    // boundary groups {0..3, 252..256}, guarded
    perc_kernel<true><<<gb, 256>>>(S, H, o1, o2);
}

// round 8
// speedup vs baseline: 9.8955x; 1.2889x over previous
#include <cuda_runtime.h>
#include <cuda_fp16.h>
#include <stdint.h>

// HPSS: harm = median_31 along W, perc = median_31 along H (zero-padded),
// soft masks m = x^2/(h^2+p^2); out = concat(S*m_h, S*m_p).
// S: (2,2,1025,1024) fp32 -> 4 images of 1025x1024.
// Medians in fp16 (2 lanes packed / 32-bit, u16x2 min/max: exact for
// non-negative fp16). Masks in fp32. Harm additionally emits a zero-padded
// fp16 copy of S so perc runs guard-free and conversion-free.

#define HALF 15
#define NIMG 4
#define HH 1025
#define WW 1024
#define NTOT (NIMG * HH * WW)   // 4,198,400

#define PADT 16                 // top pad rows in S16 (need 15)
#define PADH 1064               // padded rows per image (16 + 1025 + 23)
#define NPAD 2050               // harm row-pair blocks
#define PADBLK 8                // extra blocks that zero S16 pad rows

__device__ __half g_harm[NTOT];              // harmonic median (fp16)
__device__ __half g_s16[NIMG * PADH * WW];   // zero-padded fp16 copy of S

__device__ __forceinline__ uint32_t umin2(uint32_t a, uint32_t b) {
    uint32_t d;
    asm("min.u16x2 %0, %1, %2;" : "=r"(d) : "r"(a), "r"(b));
    return d;
}
__device__ __forceinline__ uint32_t umax2(uint32_t a, uint32_t b) {
    uint32_t d;
    asm("max.u16x2 %0, %1, %2;" : "=r"(d) : "r"(a), "r"(b));
    return d;
}
__device__ __forceinline__ void ce2(uint32_t &a, uint32_t &b) {
    uint32_t lo = umin2(a, b);
    uint32_t hi = umax2(a, b);
    a = lo;
    b = hi;
}

__device__ __forceinline__ uint32_t pack2(float x, float y) {
    __half2 h = __floats2half2_rn(x, y);
    return *reinterpret_cast<uint32_t *>(&h);
}
__device__ __forceinline__ float2 unpack2(uint32_t v) {
    __half2 h = *reinterpret_cast<__half2 *>(&v);
    return __half22float2(h);
}

// ---- compile-time Batcher network, pruned to a rank range, single-sided ----
template <int N>
constexpr int count_pairs() {
    int c = 0;
    for (int p = 1; p < N; p <<= 1)
        for (int k = p; k >= 1; k >>= 1)
            for (int j = k % p; j + k < N; j += 2 * k)
                for (int i = 0; i < k; ++i)
                    if (i + j + k < N && (i + j) / (2 * p) == (i + j + k) / (2 * p)) ++c;
    return c;
}

template <int M>
struct PairListT {
    int a[M];
    int b[M];
    int t[M];  // 3=both, 1=min-only, 2=max-only
};

template <int N, int M>
constexpr PairListT<M> make_pairs() {
    PairListT<M> L{};
    int c = 0;
    for (int p = 1; p < N; p <<= 1)
        for (int k = p; k >= 1; k >>= 1)
            for (int j = k % p; j + k < N; j += 2 * k)
                for (int i = 0; i < k; ++i)
                    if (i + j + k < N && (i + j) / (2 * p) == (i + j + k) / (2 * p)) {
                        L.a[c] = i + j;
                        L.b[c] = i + j + k;
                        L.t[c] = 3;
                        ++c;
                    }
    return L;
}

template <int N, int M>
constexpr int count_kept(const PairListT<M> &L, int lo, int hi) {
    bool need[64] = {};
    for (int i = lo; i <= hi; ++i) need[i] = true;
    int cnt = 0;
    for (int t = M - 1; t >= 0; --t)
        if (need[L.a[t]] || need[L.b[t]]) {
            ++cnt;
            need[L.a[t]] = true;
            need[L.b[t]] = true;
        }
    return cnt;
}

// Backward pass: keep a comparator iff one of its wires is needed downstream;
// record which side(s) are needed at that moment (single-sided emission).
template <int N, int M, int MK>
constexpr PairListT<MK> prune_pairs(const PairListT<M> &L, int lo, int hi) {
    bool need[64] = {};
    bool keep[512] = {};
    int ty[512] = {};
    for (int i = lo; i <= hi; ++i) need[i] = true;
    for (int t = M - 1; t >= 0; --t) {
        bool na = need[L.a[t]], nb = need[L.b[t]];
        if (na || nb) {
            keep[t] = true;
            ty[t] = (na ? 1 : 0) | (nb ? 2 : 0);
            need[L.a[t]] = true;
            need[L.b[t]] = true;
        }
    }
    PairListT<MK> R{};
    int c = 0;
    for (int t = 0; t < M; ++t)
        if (keep[t]) {
            R.a[c] = L.a[t];
            R.b[c] = L.b[t];
            R.t[c] = ty[t];
            ++c;
        }
    return R;
}

template <int N, int LO, int HI>
struct SelNet {
    static constexpr int M = count_pairs<N>();
    static constexpr PairListT<M> Lf = make_pairs<N, M>();
    static constexpr int MK = count_kept<N, M>(Lf, LO, HI);
    static constexpr PairListT<MK> L = prune_pairs<N, M, MK>(Lf, LO, HI);

    template <int I = 0>
    static __device__ __forceinline__ void run(uint32_t (&x)[N]) {
        if constexpr (I < MK) {
            constexpr int ia = L.a[I];
            constexpr int ib = L.b[I];
            constexpr int ty = L.t[I];
            if constexpr (ty == 3) {
                ce2(x[ia], x[ib]);
            } else if constexpr (ty == 1) {
                x[ia] = umin2(x[ia], x[ib]);
            } else {
                x[ib] = umax2(x[ia], x[ib]);
            }
            run<I + 1>(x);
        }
    }
};

// rank-3 of union(sorted A=(c12..c15), sorted B=(b0<=b1<=b2)), per lane
__device__ __forceinline__ uint32_t sel3(const uint32_t (&c)[28], uint32_t b0, uint32_t b1,
                                         uint32_t b2) {
    uint32_t t1 = umin2(c[13], b2);
    uint32_t t2 = umin2(c[14], b1);
    uint32_t t3 = umin2(c[15], b0);
    return umax2(umax2(c[12], t1), umax2(t2, t3));
}

// Four medians from sorted core c (ranks 12..15) and six raw extras.
__device__ __forceinline__ void four_medians(const uint32_t (&c)[28], uint32_t e0,
                                             uint32_t e1, uint32_t e2, uint32_t e3,
                                             uint32_t e4, uint32_t e5, uint32_t &m0,
                                             uint32_t &m1, uint32_t &m2, uint32_t &m3) {
    uint32_t l12 = umin2(e1, e2), h12 = umax2(e1, e2);
    uint32_t l34 = umin2(e3, e4), h34 = umax2(e3, e4);
    {
        uint32_t a = umin2(e0, l12), t = umax2(e0, l12);
        uint32_t b = umin2(t, h12), d = umax2(t, h12);
        m0 = sel3(c, a, b, d);
    }
    {
        uint32_t t = umin2(h12, e3), T = umax2(h12, e3);
        uint32_t a = umin2(l12, t), b = umax2(l12, t);
        m1 = sel3(c, a, b, T);
    }
    {
        uint32_t a = umin2(e2, l34), t = umax2(e2, l34);
        uint32_t b = umin2(t, h34), d = umax2(t, h34);
        m2 = sel3(c, a, b, d);
    }
    {
        uint32_t t = umin2(h34, e5), T = umax2(h34, e5);
        uint32_t a = umin2(l34, t), b = umax2(l34, t);
        m3 = sel3(c, a, b, T);
    }
}

// ---- harmonic: median along W (2 rows packed per lane) + emit padded S16 ----
__global__ __launch_bounds__(256, 2) void harm_kernel(const float *__restrict__ S,
                                                      __half *__restrict__ H,
                                                      __half *__restrict__ S16) {
    const int t = threadIdx.x;

    if (blockIdx.x >= NPAD) {
        // zero the S16 pad rows: per image rows [0,16) and [1041,1060)
        uint32_t *p = reinterpret_cast<uint32_t *>(S16);
        const int total = NIMG * 35 * (WW / 2);  // 71680 words
        for (int i = (blockIdx.x - NPAD) * 256 + t; i < total; i += PADBLK * 256) {
            int img = i / (35 * 512);
            int rem = i % (35 * 512);
            int row = rem / 512;
            row = (row < 16) ? row : (PADT + HH + (row - 16));  // 1041..1059
            p[(size_t)img * PADH * 512 + (size_t)row * 512 + (rem % 512)] = 0u;
        }
        return;
    }

    __shared__ __align__(16) uint32_t sm[HALF + WW + HALF + 14];  // packed rows
    const int rp = blockIdx.x;  // row pair 0..2049 (global rows 2rp, 2rp+1)
    const float *r0p = S + (size_t)(2 * rp) * WW;
    const float *r1p = r0p + WW;

    if (t < HALF) sm[t] = 0u;
    if (t < HALF + 14) sm[HALF + WW + t] = 0u;
#pragma unroll
    for (int i = 0; i < 4; ++i)
        sm[HALF + t + 256 * i] = pack2(r0p[t + 256 * i], r1p[t + 256 * i]);
    __syncthreads();

    const uint4 *wv = reinterpret_cast<const uint4 *>(&sm[4 * t]);
    uint32_t x[36];
#pragma unroll
    for (int q = 0; q < 9; ++q) {
        uint4 v = wv[q];
        x[4 * q + 0] = v.x;
        x[4 * q + 1] = v.y;
        x[4 * q + 2] = v.z;
        x[4 * q + 3] = v.w;
    }

    // emit padded fp16 copy of S for the two rows (cols 4t..4t+3 = x[15..18])
    {
        uint2 s0 = make_uint2(__byte_perm(x[15], x[16], 0x5410),
                              __byte_perm(x[17], x[18], 0x5410));
        uint2 s1 = make_uint2(__byte_perm(x[15], x[16], 0x7632),
                              __byte_perm(x[17], x[18], 0x7632));
        int R0 = 2 * rp, R1 = R0 + 1;
        int img0 = R0 / HH, r0 = R0 - img0 * HH;
        int img1 = R1 / HH, r1 = R1 - img1 * HH;
        *reinterpret_cast<uint2 *>(S16 + ((size_t)img0 * PADH + PADT + r0) * WW + 4 * t) = s0;
        *reinterpret_cast<uint2 *>(S16 + ((size_t)img1 * PADH + PADT + r1) * WW + 4 * t) = s1;
    }

    uint32_t c[28];
#pragma unroll
    for (int i = 0; i < 28; ++i) c[i] = x[3 + i];
    SelNet<28, 12, 15>::run(c);

    uint32_t m0, m1, m2, m3;
    four_medians(c, x[0], x[1], x[2], x[31], x[32], x[33], m0, m1, m2, m3);

    uint2 row0 = make_uint2(__byte_perm(m0, m1, 0x5410), __byte_perm(m2, m3, 0x5410));
    uint2 row1 = make_uint2(__byte_perm(m0, m1, 0x7632), __byte_perm(m2, m3, 0x7632));
    *reinterpret_cast<uint2 *>(H + (size_t)(2 * rp) * WW + 4 * t) = row0;
    *reinterpret_cast<uint2 *>(H + (size_t)(2 * rp + 1) * WW + 4 * t) = row1;
}

// ---- percussive: median along H from padded S16 (guard-free), fused mask ----
__global__ __launch_bounds__(256, 2) void perc_kernel(const float *__restrict__ S,
                                                      const __half *__restrict__ H,
                                                      const __half *__restrict__ S16,
                                                      float *__restrict__ o1,
                                                      float *__restrict__ o2) {
    const int cp = blockIdx.x * 256 + threadIdx.x;  // column pair 0..511
    const int col = 2 * cp;
    const int g = blockIdx.y;   // 0..256
    const int img = blockIdx.z; // 0..3

    // padded row of window start: r0 = g*4-15 -> p0 = g*4+1 (always >= 1)
    const int p0 = g * 4 + 1;
    const uint32_t *Pp = reinterpret_cast<const uint32_t *>(
        S16 + ((size_t)img * PADH + p0) * WW + col);

    uint32_t c[28];
#pragma unroll
    for (int i = 0; i < 28; ++i) c[i] = Pp[(size_t)(3 + i) * (WW / 2)];
    SelNet<28, 12, 15>::run(c);

    uint32_t ex[6];
#pragma unroll
    for (int i = 0; i < 6; ++i) {
        int off = (i < 3) ? i : (28 + i);  // 0,1,2,31,32,33
        ex[i] = Pp[(size_t)off * (WW / 2)];
    }

    uint32_t m[4];
    four_medians(c, ex[0], ex[1], ex[2], ex[3], ex[4], ex[5], m[0], m[1], m[2], m[3]);

    const float *Sp = S + (size_t)img * HH * WW + col;
    const bool full = (g * 4 + 3 < HH);  // uniform per block; false only for g==256

#pragma unroll
    for (int i = 0; i < 4; ++i) {
        int r = g * 4 + i;
        if (full || r < HH) {
            size_t idx = (size_t)img * HH * WW + (size_t)r * WW + col;
            float2 s = *reinterpret_cast<const float2 *>(&Sp[(size_t)r * WW]);
            float2 hf = unpack2(*reinterpret_cast<const uint32_t *>(&H[idx]));
            float2 pf = unpack2(m[i]);
            float2 r1, r2;
            {
                float h = hf.x, p = pf.x;
                float Z = fmaxf(h, p);
                if (Z < 1.17549435e-38f) Z = 1.0f;
                float zi = 1.0f / Z;
                float a = h * zi, b = p * zi;
                float a2 = a * a, b2 = b * b;
                float di = 1.0f / (a2 + b2);
                r1.x = s.x * (a2 * di);
                r2.x = s.x * (b2 * di);
            }
            {
                float h = hf.y, p = pf.y;
                float Z = fmaxf(h, p);
                if (Z < 1.17549435e-38f) Z = 1.0f;
                float zi = 1.0f / Z;
                float a = h * zi, b = p * zi;
                float a2 = a * a, b2 = b * b;
                float di = 1.0f / (a2 + b2);
                r1.y = s.y * (a2 * di);
                r2.y = s.y * (b2 * di);
            }
            *reinterpret_cast<float2 *>(&o1[idx]) = r1;
            *reinterpret_cast<float2 *>(&o2[idx]) = r2;
        }
    }
}

extern "C" void kernel_launch(void *const *d_in, const int *in_sizes, int n_in,
                              void *d_out, int out_size) {
    const float *S = (const float *)d_in[0];
    float *out = (float *)d_out;
    float *o1 = out;          // S * mask_harm
    float *o2 = out + NTOT;   // S * mask_perc

    __half *H, *S16;
    cudaGetSymbolAddress((void **)&H, g_harm);
    cudaGetSymbolAddress((void **)&S16, g_s16);

    harm_kernel<<<NPAD + PADBLK, 256>>>(S, H, S16);

    dim3 gp(2, 257, NIMG);
    perc_kernel<<<gp, 256>>>(S, H, S16, o1, o2);
}

// round 9
// speedup vs baseline: 10.5092x; 1.0620x over previous
#include <cuda_runtime.h>
#include <cuda_fp16.h>
#include <stdint.h>

// HPSS: harm = median_31 along W, perc = median_31 along H (zero-padded),
// soft masks m_h = h^2/(h^2+p^2), m_p = p^2/(h^2+p^2); out = concat(S*m_h, S*m_p).
// S: (2,2,1025,1024) fp32 -> 4 images of 1025x1024.
// Medians in fp16 (2 lanes packed / 32-bit, u16x2 min/max: exact for
// non-negative fp16). Harm emits a zero-padded fp16 copy of S so perc runs
// guard-free and conversion-free; perc's S multiplier comes from the core
// registers (fp16), masks via one rcp.approx per lane.

#define HALF 15
#define NIMG 4
#define HH 1025
#define WW 1024
#define NTOT (NIMG * HH * WW)   // 4,198,400

#define PADT 16                 // top pad rows in S16 (need 15)
#define PADH 1064               // padded rows per image (16 + 1025 + 23)
#define NPAD 2050               // harm row-pair blocks
#define PADBLK 8                // extra blocks that zero S16 pad rows

__device__ __half g_harm[NTOT];              // harmonic median (fp16)
__device__ __half g_s16[NIMG * PADH * WW];   // zero-padded fp16 copy of S

__device__ __forceinline__ uint32_t umin2(uint32_t a, uint32_t b) {
    uint32_t d;
    asm("min.u16x2 %0, %1, %2;" : "=r"(d) : "r"(a), "r"(b));
    return d;
}
__device__ __forceinline__ uint32_t umax2(uint32_t a, uint32_t b) {
    uint32_t d;
    asm("max.u16x2 %0, %1, %2;" : "=r"(d) : "r"(a), "r"(b));
    return d;
}
__device__ __forceinline__ void ce2(uint32_t &a, uint32_t &b) {
    uint32_t lo = umin2(a, b);
    uint32_t hi = umax2(a, b);
    a = lo;
    b = hi;
}

__device__ __forceinline__ uint32_t pack2(float x, float y) {
    __half2 h = __floats2half2_rn(x, y);
    return *reinterpret_cast<uint32_t *>(&h);
}
__device__ __forceinline__ float2 unpack2(uint32_t v) {
    __half2 h = *reinterpret_cast<__half2 *>(&v);
    return __half22float2(h);
}
__device__ __forceinline__ float frcp(float x) {
    float r;
    asm("rcp.approx.f32 %0, %1;" : "=f"(r) : "f"(x));
    return r;
}

// ---- compile-time Batcher network, pruned to a rank range, single-sided ----
template <int N>
constexpr int count_pairs() {
    int c = 0;
    for (int p = 1; p < N; p <<= 1)
        for (int k = p; k >= 1; k >>= 1)
            for (int j = k % p; j + k < N; j += 2 * k)
                for (int i = 0; i < k; ++i)
                    if (i + j + k < N && (i + j) / (2 * p) == (i + j + k) / (2 * p)) ++c;
    return c;
}

template <int M>
struct PairListT {
    int a[M];
    int b[M];
    int t[M];  // 3=both, 1=min-only, 2=max-only
};

template <int N, int M>
constexpr PairListT<M> make_pairs() {
    PairListT<M> L{};
    int c = 0;
    for (int p = 1; p < N; p <<= 1)
        for (int k = p; k >= 1; k >>= 1)
            for (int j = k % p; j + k < N; j += 2 * k)
                for (int i = 0; i < k; ++i)
                    if (i + j + k < N && (i + j) / (2 * p) == (i + j + k) / (2 * p)) {
                        L.a[c] = i + j;
                        L.b[c] = i + j + k;
                        L.t[c] = 3;
                        ++c;
                    }
    return L;
}

template <int N, int M>
constexpr int count_kept(const PairListT<M> &L, int lo, int hi) {
    bool need[64] = {};
    for (int i = lo; i <= hi; ++i) need[i] = true;
    int cnt = 0;
    for (int t = M - 1; t >= 0; --t)
        if (need[L.a[t]] || need[L.b[t]]) {
            ++cnt;
            need[L.a[t]] = true;
            need[L.b[t]] = true;
        }
    return cnt;
}

template <int N, int M, int MK>
constexpr PairListT<MK> prune_pairs(const PairListT<M> &L, int lo, int hi) {
    bool need[64] = {};
    bool keep[512] = {};
    int ty[512] = {};
    for (int i = lo; i <= hi; ++i) need[i] = true;
    for (int t = M - 1; t >= 0; --t) {
        bool na = need[L.a[t]], nb = need[L.b[t]];
        if (na || nb) {
            keep[t] = true;
            ty[t] = (na ? 1 : 0) | (nb ? 2 : 0);
            need[L.a[t]] = true;
            need[L.b[t]] = true;
        }
    }
    PairListT<MK> R{};
    int c = 0;
    for (int t = 0; t < M; ++t)
        if (keep[t]) {
            R.a[c] = L.a[t];
            R.b[c] = L.b[t];
            R.t[c] = ty[t];
            ++c;
        }
    return R;
}

template <int N, int LO, int HI>
struct SelNet {
    static constexpr int M = count_pairs<N>();
    static constexpr PairListT<M> Lf = make_pairs<N, M>();
    static constexpr int MK = count_kept<N, M>(Lf, LO, HI);
    static constexpr PairListT<MK> L = prune_pairs<N, M, MK>(Lf, LO, HI);

    template <int I = 0>
    static __device__ __forceinline__ void run(uint32_t (&x)[N]) {
        if constexpr (I < MK) {
            constexpr int ia = L.a[I];
            constexpr int ib = L.b[I];
            constexpr int ty = L.t[I];
            if constexpr (ty == 3) {
                ce2(x[ia], x[ib]);
            } else if constexpr (ty == 1) {
                x[ia] = umin2(x[ia], x[ib]);
            } else {
                x[ib] = umax2(x[ia], x[ib]);
            }
            run<I + 1>(x);
        }
    }
};

// rank-3 of union(sorted A=(c12..c15), sorted B=(b0<=b1<=b2)), per lane
__device__ __forceinline__ uint32_t sel3(const uint32_t (&c)[28], uint32_t b0, uint32_t b1,
                                         uint32_t b2) {
    uint32_t t1 = umin2(c[13], b2);
    uint32_t t2 = umin2(c[14], b1);
    uint32_t t3 = umin2(c[15], b0);
    return umax2(umax2(c[12], t1), umax2(t2, t3));
}

// Four medians from sorted core c (ranks 12..15) and six raw extras.
__device__ __forceinline__ void four_medians(const uint32_t (&c)[28], uint32_t e0,
                                             uint32_t e1, uint32_t e2, uint32_t e3,
                                             uint32_t e4, uint32_t e5, uint32_t &m0,
                                             uint32_t &m1, uint32_t &m2, uint32_t &m3) {
    uint32_t l12 = umin2(e1, e2), h12 = umax2(e1, e2);
    uint32_t l34 = umin2(e3, e4), h34 = umax2(e3, e4);
    {
        uint32_t a = umin2(e0, l12), t = umax2(e0, l12);
        uint32_t b = umin2(t, h12), d = umax2(t, h12);
        m0 = sel3(c, a, b, d);
    }
    {
        uint32_t t = umin2(h12, e3), T = umax2(h12, e3);
        uint32_t a = umin2(l12, t), b = umax2(l12, t);
        m1 = sel3(c, a, b, T);
    }
    {
        uint32_t a = umin2(e2, l34), t = umax2(e2, l34);
        uint32_t b = umin2(t, h34), d = umax2(t, h34);
        m2 = sel3(c, a, b, d);
    }
    {
        uint32_t t = umin2(h34, e5), T = umax2(h34, e5);
        uint32_t a = umin2(l34, t), b = umax2(l34, t);
        m3 = sel3(c, a, b, T);
    }
}

// ---- harmonic: median along W (2 rows packed per lane) + emit padded S16 ----
__global__ __launch_bounds__(256, 2) void harm_kernel(const float *__restrict__ S,
                                                      __half *__restrict__ H,
                                                      __half *__restrict__ S16) {
    const int t = threadIdx.x;

    if (blockIdx.x >= NPAD) {
        // zero the S16 pad rows: per image rows [0,16) and [1041,1060)
        uint32_t *p = reinterpret_cast<uint32_t *>(S16);
        const int total = NIMG * 35 * (WW / 2);  // 71680 words
        for (int i = (blockIdx.x - NPAD) * 256 + t; i < total; i += PADBLK * 256) {
            int img = i / (35 * 512);
            int rem = i % (35 * 512);
            int row = rem / 512;
            row = (row < 16) ? row : (PADT + HH + (row - 16));  // 1041..1059
            p[(size_t)img * PADH * 512 + (size_t)row * 512 + (rem % 512)] = 0u;
        }
        return;
    }

    __shared__ __align__(16) uint32_t sm[HALF + WW + HALF + 14];  // packed rows
    const int rp = blockIdx.x;  // row pair 0..2049 (global rows 2rp, 2rp+1)
    const float *r0p = S + (size_t)(2 * rp) * WW;
    const float *r1p = r0p + WW;

    if (t < HALF) sm[t] = 0u;
    if (t < HALF + 14) sm[HALF + WW + t] = 0u;
#pragma unroll
    for (int i = 0; i < 4; ++i)
        sm[HALF + t + 256 * i] = pack2(r0p[t + 256 * i], r1p[t + 256 * i]);
    __syncthreads();

    const uint4 *wv = reinterpret_cast<const uint4 *>(&sm[4 * t]);
    uint32_t x[36];
#pragma unroll
    for (int q = 0; q < 9; ++q) {
        uint4 v = wv[q];
        x[4 * q + 0] = v.x;
        x[4 * q + 1] = v.y;
        x[4 * q + 2] = v.z;
        x[4 * q + 3] = v.w;
    }

    // emit padded fp16 copy of S for the two rows (cols 4t..4t+3 = x[15..18])
    {
        uint2 s0 = make_uint2(__byte_perm(x[15], x[16], 0x5410),
                              __byte_perm(x[17], x[18], 0x5410));
        uint2 s1 = make_uint2(__byte_perm(x[15], x[16], 0x7632),
                              __byte_perm(x[17], x[18], 0x7632));
        int R0 = 2 * rp, R1 = R0 + 1;
        int img0 = R0 / HH, r0 = R0 - img0 * HH;
        int img1 = R1 / HH, r1 = R1 - img1 * HH;
        *reinterpret_cast<uint2 *>(S16 + ((size_t)img0 * PADH + PADT + r0) * WW + 4 * t) = s0;
        *reinterpret_cast<uint2 *>(S16 + ((size_t)img1 * PADH + PADT + r1) * WW + 4 * t) = s1;
    }

    uint32_t c[28];
#pragma unroll
    for (int i = 0; i < 28; ++i) c[i] = x[3 + i];
    SelNet<28, 12, 15>::run(c);

    uint32_t m0, m1, m2, m3;
    four_medians(c, x[0], x[1], x[2], x[31], x[32], x[33], m0, m1, m2, m3);

    uint2 row0 = make_uint2(__byte_perm(m0, m1, 0x5410), __byte_perm(m2, m3, 0x5410));
    uint2 row1 = make_uint2(__byte_perm(m0, m1, 0x7632), __byte_perm(m2, m3, 0x7632));
    *reinterpret_cast<uint2 *>(H + (size_t)(2 * rp) * WW + 4 * t) = row0;
    *reinterpret_cast<uint2 *>(H + (size_t)(2 * rp + 1) * WW + 4 * t) = row1;
}

// ---- percussive: median along H from padded S16 (guard-free), fused mask ----
__global__ __launch_bounds__(256, 2) void perc_kernel(const __half *__restrict__ H,
                                                      const __half *__restrict__ S16,
                                                      float *__restrict__ o1,
                                                      float *__restrict__ o2) {
    const int cp = blockIdx.x * 256 + threadIdx.x;  // column pair 0..511
    const int col = 2 * cp;
    const int g = blockIdx.y;   // 0..256
    const int img = blockIdx.z; // 0..3

    // padded row of window start: r0 = g*4-15 -> p0 = g*4+1 (always >= 1)
    const int p0 = g * 4 + 1;
    const uint32_t *Pp = reinterpret_cast<const uint32_t *>(
        S16 + ((size_t)img * PADH + p0) * WW + col);

    uint32_t c[28];
#pragma unroll
    for (int i = 0; i < 28; ++i) c[i] = Pp[(size_t)(3 + i) * (WW / 2)];

    // S at the 4 output rows == core positions 12..15, saved before the sort
    uint32_t ssav[4];
#pragma unroll
    for (int i = 0; i < 4; ++i) ssav[i] = c[12 + i];

    SelNet<28, 12, 15>::run(c);

    uint32_t ex[6];
#pragma unroll
    for (int i = 0; i < 6; ++i) {
        int off = (i < 3) ? i : (28 + i);  // 0,1,2,31,32,33
        ex[i] = Pp[(size_t)off * (WW / 2)];
    }

    uint32_t m[4];
    four_medians(c, ex[0], ex[1], ex[2], ex[3], ex[4], ex[5], m[0], m[1], m[2], m[3]);

    const bool full = (g * 4 + 3 < HH);  // uniform per block; false only for g==256

#pragma unroll
    for (int i = 0; i < 4; ++i) {
        int r = g * 4 + i;
        if (full || r < HH) {
            size_t idx = (size_t)img * HH * WW + (size_t)r * WW + col;
            float2 s = unpack2(ssav[i]);
            float2 hf = unpack2(*reinterpret_cast<const uint32_t *>(&H[idx]));
            float2 pf = unpack2(m[i]);
            float2 r1, r2;
            {
                float a2 = hf.x * hf.x;
                float b2 = pf.x * pf.x;
                float di = frcp(a2 + b2);
                r1.x = s.x * (a2 * di);
                r2.x = s.x * (b2 * di);
            }
            {
                float a2 = hf.y * hf.y;
                float b2 = pf.y * pf.y;
                float di = frcp(a2 + b2);
                r1.y = s.y * (a2 * di);
                r2.y = s.y * (b2 * di);
            }
            *reinterpret_cast<float2 *>(&o1[idx]) = r1;
            *reinterpret_cast<float2 *>(&o2[idx]) = r2;
        }
    }
}

extern "C" void kernel_launch(void *const *d_in, const int *in_sizes, int n_in,
                              void *d_out, int out_size) {
    const float *S = (const float *)d_in[0];
    float *out = (float *)d_out;
    float *o1 = out;          // S * mask_harm
    float *o2 = out + NTOT;   // S * mask_perc

    __half *H, *S16;
    cudaGetSymbolAddress((void **)&H, g_harm);
    cudaGetSymbolAddress((void **)&S16, g_s16);

    harm_kernel<<<NPAD + PADBLK, 256>>>(S, H, S16);

    dim3 gp(2, 257, NIMG);
    perc_kernel<<<gp, 256>>>(H, S16, o1, o2);
}

// round 12
// speedup vs baseline: 10.7550x; 1.0234x over previous
#include <cuda_runtime.h>
#include <cuda_fp16.h>
#include <stdint.h>

// HPSS: harm = median_31 along W, perc = median_31 along H (zero-padded),
// soft masks m_h = h^2/(h^2+p^2), m_p = p^2/(h^2+p^2); out = concat(S*m_h, S*m_p).
// S: (2,2,1025,1024) fp32 -> 4 images of 1025x1024.
// Medians in fp16 (2 lanes packed / u16x2 min/max, exact for non-negative).
// Each thread runs TWO interleaved comparator pipelines (ILP=2) to cover the
// 4-cycle alu RAW latency that capped issue at ~50%.

#define HALF 15
#define NIMG 4
#define HH 1025
#define WW 1024
#define NTOT (NIMG * HH * WW)   // 4,198,400

#define PADT 16                 // top pad rows in S16 (need 15)
#define PADH 1064               // padded rows per image
#define NBLK 1025               // harm 4-row blocks (4100/4)
#define PADBLK 8                // extra blocks that zero S16 pad rows

__device__ __half g_harm[NTOT];              // harmonic median (fp16)
__device__ __half g_s16[NIMG * PADH * WW];   // zero-padded fp16 copy of S

__device__ __forceinline__ uint32_t umin2(uint32_t a, uint32_t b) {
    uint32_t d;
    asm("min.u16x2 %0, %1, %2;" : "=r"(d) : "r"(a), "r"(b));
    return d;
}
__device__ __forceinline__ uint32_t umax2(uint32_t a, uint32_t b) {
    uint32_t d;
    asm("max.u16x2 %0, %1, %2;" : "=r"(d) : "r"(a), "r"(b));
    return d;
}
__device__ __forceinline__ void ce2(uint32_t &a, uint32_t &b) {
    uint32_t lo = umin2(a, b);
    uint32_t hi = umax2(a, b);
    a = lo;
    b = hi;
}

__device__ __forceinline__ uint32_t pack2(float x, float y) {
    __half2 h = __floats2half2_rn(x, y);
    return *reinterpret_cast<uint32_t *>(&h);
}
__device__ __forceinline__ float2 unpack2(uint32_t v) {
    __half2 h = *reinterpret_cast<__half2 *>(&v);
    return __half22float2(h);
}
__device__ __forceinline__ float frcp(float x) {
    float r;
    asm("rcp.approx.f32 %0, %1;" : "=f"(r) : "f"(x));
    return r;
}

// ---- compile-time Batcher network, pruned to a rank range, single-sided ----
template <int N>
constexpr int count_pairs() {
    int c = 0;
    for (int p = 1; p < N; p <<= 1)
        for (int k = p; k >= 1; k >>= 1)
            for (int j = k % p; j + k < N; j += 2 * k)
                for (int i = 0; i < k; ++i)
                    if (i + j + k < N && (i + j) / (2 * p) == (i + j + k) / (2 * p)) ++c;
    return c;
}

template <int M>
struct PairListT {
    int a[M];
    int b[M];
    int t[M];  // 3=both, 1=min-only, 2=max-only
};

template <int N, int M>
constexpr PairListT<M> make_pairs() {
    PairListT<M> L{};
    int c = 0;
    for (int p = 1; p < N; p <<= 1)
        for (int k = p; k >= 1; k >>= 1)
            for (int j = k % p; j + k < N; j += 2 * k)
                for (int i = 0; i < k; ++i)
                    if (i + j + k < N && (i + j) / (2 * p) == (i + j + k) / (2 * p)) {
                        L.a[c] = i + j;
                        L.b[c] = i + j + k;
                        L.t[c] = 3;
                        ++c;
                    }
    return L;
}

template <int N, int M>
constexpr int count_kept(const PairListT<M> &L, int lo, int hi) {
    bool need[64] = {};
    for (int i = lo; i <= hi; ++i) need[i] = true;
    int cnt = 0;
    for (int t = M - 1; t >= 0; --t)
        if (need[L.a[t]] || need[L.b[t]]) {
            ++cnt;
            need[L.a[t]] = true;
            need[L.b[t]] = true;
        }
    return cnt;
}

template <int N, int M, int MK>
constexpr PairListT<MK> prune_pairs(const PairListT<M> &L, int lo, int hi) {
    bool need[64] = {};
    bool keep[512] = {};
    int ty[512] = {};
    for (int i = lo; i <= hi; ++i) need[i] = true;
    for (int t = M - 1; t >= 0; --t) {
        bool na = need[L.a[t]], nb = need[L.b[t]];
        if (na || nb) {
            keep[t] = true;
            ty[t] = (na ? 1 : 0) | (nb ? 2 : 0);
            need[L.a[t]] = true;
            need[L.b[t]] = true;
        }
    }
    PairListT<MK> R{};
    int c = 0;
    for (int t = 0; t < M; ++t)
        if (keep[t]) {
            R.a[c] = L.a[t];
            R.b[c] = L.b[t];
            R.t[c] = ty[t];
            ++c;
        }
    return R;
}

template <int N, int LO, int HI>
struct SelNet {
    static constexpr int M = count_pairs<N>();
    static constexpr PairListT<M> Lf = make_pairs<N, M>();
    static constexpr int MK = count_kept<N, M>(Lf, LO, HI);
    static constexpr PairListT<MK> L = prune_pairs<N, M, MK>(Lf, LO, HI);

    template <int I = 0>
    static __device__ __forceinline__ void step(uint32_t (&x)[N]) {
        constexpr int ia = L.a[I];
        constexpr int ib = L.b[I];
        constexpr int ty = L.t[I];
        if constexpr (ty == 3) {
            ce2(x[ia], x[ib]);
        } else if constexpr (ty == 1) {
            x[ia] = umin2(x[ia], x[ib]);
        } else {
            x[ib] = umax2(x[ia], x[ib]);
        }
    }

    // two independent pipelines, op-interleaved for guaranteed ILP=2
    template <int I = 0>
    static __device__ __forceinline__ void run2(uint32_t (&x)[N], uint32_t (&y)[N]) {
        if constexpr (I < MK) {
            step<I>(x);
            step<I>(y);
            run2<I + 1>(x, y);
        }
    }
};

// rank-3 of union(sorted A=(c12..c15), sorted B=(b0<=b1<=b2)), per lane
__device__ __forceinline__ uint32_t sel3(const uint32_t (&c)[28], uint32_t b0, uint32_t b1,
                                         uint32_t b2) {
    uint32_t t1 = umin2(c[13], b2);
    uint32_t t2 = umin2(c[14], b1);
    uint32_t t3 = umin2(c[15], b0);
    return umax2(umax2(c[12], t1), umax2(t2, t3));
}

// Four medians from sorted core c (ranks 12..15) and six raw extras e[6].
__device__ __forceinline__ void four_medians(const uint32_t (&c)[28], const uint32_t (&e)[6],
                                             uint32_t (&m)[4]) {
    uint32_t l12 = umin2(e[1], e[2]), h12 = umax2(e[1], e[2]);
    uint32_t l34 = umin2(e[3], e[4]), h34 = umax2(e[3], e[4]);
    {
        uint32_t a = umin2(e[0], l12), t = umax2(e[0], l12);
        uint32_t b = umin2(t, h12), d = umax2(t, h12);
        m[0] = sel3(c, a, b, d);
    }
    {
        uint32_t t = umin2(h12, e[3]), T = umax2(h12, e[3]);
        uint32_t a = umin2(l12, t), b = umax2(l12, t);
        m[1] = sel3(c, a, b, T);
    }
    {
        uint32_t a = umin2(e[2], l34), t = umax2(e[2], l34);
        uint32_t b = umin2(t, h34), d = umax2(t, h34);
        m[2] = sel3(c, a, b, d);
    }
    {
        uint32_t t = umin2(h34, e[5]), T = umax2(h34, e[5]);
        uint32_t a = umin2(l34, t), b = umax2(l34, t);
        m[3] = sel3(c, a, b, T);
    }
}

// ---- harmonic: 4 rows per block (2 packed pipelines/thread) + padded S16 ----
__global__ __launch_bounds__(256, 2) void harm_kernel(const float *__restrict__ S,
                                                      __half *__restrict__ H,
                                                      __half *__restrict__ S16) {
    const int t = threadIdx.x;

    if (blockIdx.x >= NBLK) {
        // zero the S16 pad rows: per image rows [0,16) and [1041,1060)
        uint32_t *p = reinterpret_cast<uint32_t *>(S16);
        const int total = NIMG * 35 * (WW / 2);  // 71680 words
        for (int i = (blockIdx.x - NBLK) * 256 + t; i < total; i += PADBLK * 256) {
            int img = i / (35 * 512);
            int rem = i % (35 * 512);
            int row = rem / 512;
            row = (row < 16) ? row : (PADT + HH + (row - 16));  // 1041..1059
            p[(size_t)img * PADH * 512 + (size_t)row * 512 + (rem % 512)] = 0u;
        }
        return;
    }

    __shared__ __align__(16) uint32_t smA[HALF + WW + HALF + 14];
    __shared__ __align__(16) uint32_t smB[HALF + WW + HALF + 14];
    const int R0 = 4 * blockIdx.x;  // rows R0..R0+3
    const float *r0p = S + (size_t)R0 * WW;
    const float *r1p = r0p + WW;
    const float *r2p = r1p + WW;
    const float *r3p = r2p + WW;

    if (t < HALF) { smA[t] = 0u; smB[t] = 0u; }
    if (t < HALF + 14) { smA[HALF + WW + t] = 0u; smB[HALF + WW + t] = 0u; }
#pragma unroll
    for (int i = 0; i < 4; ++i) {
        int o = t + 256 * i;
        smA[HALF + o] = pack2(r0p[o], r1p[o]);
        smB[HALF + o] = pack2(r2p[o], r3p[o]);
    }
    __syncthreads();

    uint32_t cA[28], cB[28], eA[6], eB[6], sA[4], sB[4];
    {
        const uint4 *wa = reinterpret_cast<const uint4 *>(&smA[4 * t]);
        const uint4 *wb = reinterpret_cast<const uint4 *>(&smB[4 * t]);
#pragma unroll
        for (int q = 0; q < 9; ++q) {
            uint4 va = wa[q];
            uint4 vb = wb[q];
            uint32_t ua[4] = {va.x, va.y, va.z, va.w};
            uint32_t ub[4] = {vb.x, vb.y, vb.z, vb.w};
#pragma unroll
            for (int k = 0; k < 4; ++k) {
                int idx = 4 * q + k;
                if (idx < 3) { eA[idx] = ua[k]; eB[idx] = ub[k]; }
                if (idx >= 3 && idx <= 30) { cA[idx - 3] = ua[k]; cB[idx - 3] = ub[k]; }
                if (idx >= 31 && idx <= 33) { eA[idx - 28] = ua[k]; eB[idx - 28] = ub[k]; }
                if (idx >= 15 && idx <= 18) { sA[idx - 15] = ua[k]; sB[idx - 15] = ub[k]; }
            }
        }
    }

    // emit padded fp16 copy of S (4 rows, cols 4t..4t+3)
    {
#pragma unroll
        for (int j = 0; j < 4; ++j) {
            int R = R0 + j;
            int img = R / HH, r = R - img * HH;
            const uint32_t *sv = (j < 2) ? sA : sB;
            uint2 w;
            if ((j & 1) == 0)
                w = make_uint2(__byte_perm(sv[0], sv[1], 0x5410),
                               __byte_perm(sv[2], sv[3], 0x5410));
            else
                w = make_uint2(__byte_perm(sv[0], sv[1], 0x7632),
                               __byte_perm(sv[2], sv[3], 0x7632));
            *reinterpret_cast<uint2 *>(S16 + ((size_t)img * PADH + PADT + r) * WW + 4 * t) = w;
        }
    }

    SelNet<28, 12, 15>::run2(cA, cB);

    uint32_t mA[4], mB[4];
    four_medians(cA, eA, mA);
    four_medians(cB, eB, mB);

#pragma unroll
    for (int j = 0; j < 4; ++j) {
        const uint32_t *mv = (j < 2) ? mA : mB;
        uint2 w;
        if ((j & 1) == 0)
            w = make_uint2(__byte_perm(mv[0], mv[1], 0x5410),
                           __byte_perm(mv[2], mv[3], 0x5410));
        else
            w = make_uint2(__byte_perm(mv[0], mv[1], 0x7632),
                           __byte_perm(mv[2], mv[3], 0x7632));
        *reinterpret_cast<uint2 *>(H + (size_t)(R0 + j) * WW + 4 * t) = w;
    }
}

// ---- percussive: col-quad per thread (2 packed pipelines), fused mask ----
__global__ __launch_bounds__(256, 2) void perc_kernel(const __half *__restrict__ H,
                                                      const __half *__restrict__ S16,
                                                      float *__restrict__ o1,
                                                      float *__restrict__ o2) {
    const int t = threadIdx.x;   // col quad 0..255 -> cols 4t..4t+3
    const int g = blockIdx.y;    // 0..256
    const int img = blockIdx.z;  // 0..3

    const int p0 = g * 4 + 1;  // padded row of window start (r0 = g*4-15)
    const uint2 *P2 = reinterpret_cast<const uint2 *>(
                          S16 + ((size_t)img * PADH + p0) * WW) + t;

    uint32_t cA[28], cB[28];
#pragma unroll
    for (int i = 0; i < 28; ++i) {
        uint2 v = P2[(size_t)(3 + i) * 256];
        cA[i] = v.x;
        cB[i] = v.y;
    }

    // S at the 4 output rows == core positions 12..15, saved before the sort
    uint32_t ssA[4], ssB[4];
#pragma unroll
    for (int i = 0; i < 4; ++i) { ssA[i] = cA[12 + i]; ssB[i] = cB[12 + i]; }

    uint32_t eA[6], eB[6];
#pragma unroll
    for (int i = 0; i < 6; ++i) {
        int off = (i < 3) ? i : (28 + i);  // 0,1,2,31,32,33
        uint2 v = P2[(size_t)off * 256];
        eA[i] = v.x;
        eB[i] = v.y;
    }

    SelNet<28, 12, 15>::run2(cA, cB);

    uint32_t mA[4], mB[4];
    four_medians(cA, eA, mA);
    four_medians(cB, eB, mB);

    const bool full = (g * 4 + 3 < HH);  // false only for g==256

#pragma unroll
    for (int i = 0; i < 4; ++i) {
        int r = g * 4 + i;
        if (full || r < HH) {
            size_t idx = (size_t)img * HH * WW + (size_t)r * WW + 4 * t;
            uint2 hv = *reinterpret_cast<const uint2 *>(&H[idx]);
            float2 hA = unpack2(hv.x), hB = unpack2(hv.y);
            float2 pA = unpack2(mA[i]), pB = unpack2(mB[i]);
            float2 sa = unpack2(ssA[i]), sb = unpack2(ssB[i]);
            float4 r1, r2;
            {
                float a2 = hA.x * hA.x, b2 = pA.x * pA.x;
                float di = frcp(a2 + b2);
                r1.x = sa.x * (a2 * di);
                r2.x = sa.x * (b2 * di);
            }
            {
                float a2 = hA.y * hA.y, b2 = pA.y * pA.y;
                float di = frcp(a2 + b2);
                r1.y = sa.y * (a2 * di);
                r2.y = sa.y * (b2 * di);
            }
            {
                float a2 = hB.x * hB.x, b2 = pB.x * pB.x;
                float di = frcp(a2 + b2);
                r1.z = sb.x * (a2 * di);
                r2.z = sb.x * (b2 * di);
            }
            {
                float a2 = hB.y * hB.y, b2 = pB.y * pB.y;
                float di = frcp(a2 + b2);
                r1.w = sb.y * (a2 * di);
                r2.w = sb.y * (b2 * di);
            }
            *reinterpret_cast<float4 *>(&o1[idx]) = r1;
            *reinterpret_cast<float4 *>(&o2[idx]) = r2;
        }
    }
}

extern "C" void kernel_launch(void *const *d_in, const int *in_sizes, int n_in,
                              void *d_out, int out_size) {
    const float *S = (const float *)d_in[0];
    float *out = (float *)d_out;
    float *o1 = out;          // S * mask_harm
    float *o2 = out + NTOT;   // S * mask_perc

    __half *H, *S16;
    cudaGetSymbolAddress((void **)&H, g_harm);
    cudaGetSymbolAddress((void **)&S16, g_s16);

    harm_kernel<<<NBLK + PADBLK, 256>>>(S, H, S16);

    dim3 gp(1, 257, NIMG);
    perc_kernel<<<gp, 256>>>(H, S16, o1, o2);
}